// round 6
// baseline (speedup 1.0000x reference)
#include <cuda_runtime.h>
#include <cuda_bf16.h>
#include <math.h>
#include <stdint.h>

// Problem constants (fixed by setup_inputs)
#define NV 16384
#define GRP 32
#define NGROUPS 512
#define D 256
#define NH 8
#define HD 32
#define DI 1024
#define D_QKV 768
#define LN_EPS 1e-12f

// ---------------- scratch (device globals; no allocation allowed) ----------
__device__ __nv_bfloat16 g_Xhi[NV * D], g_Xlo[NV * D];
__device__ float         g_qkv[NV * D_QKV];
__device__ __nv_bfloat16 g_atthi[NV * D], g_attlo[NV * D];
__device__ float         g_tmp1[NV * D];
__device__ float         g_pre[NV * D];
__device__ __nv_bfloat16 g_prehi[NV * D], g_prelo[NV * D];
__device__ __nv_bfloat16 g_interhi[NV * DI], g_interlo[NV * DI];
__device__ float         g_tmp2[NV * D];
__device__ __nv_bfloat16 g_Wqkv_hi[D_QKV * D], g_Wqkv_lo[D_QKV * D];
__device__ __nv_bfloat16 g_Wo_hi[D * D],       g_Wo_lo[D * D];
__device__ __nv_bfloat16 g_Wi_hi[DI * D],      g_Wi_lo[DI * D];
__device__ __nv_bfloat16 g_W2_hi[D * DI],      g_W2_lo[D * DI];

// ---------------- helpers ---------------------------------------------------
__device__ __forceinline__ uint32_t smem_u32(const void* p) {
    uint32_t a;
    asm("{ .reg .u64 t; cvta.to.shared.u64 t, %1; cvt.u32.u64 %0, t; }" : "=r"(a) : "l"(p));
    return a;
}
__device__ __forceinline__ uint32_t sw128(uint32_t x) { return x ^ ((x >> 3) & 0x70); }

#define LDSM4(r0, r1, r2, r3, addr) \
    asm volatile("ldmatrix.sync.aligned.m8n8.x4.shared.b16 {%0,%1,%2,%3}, [%4];" \
                 : "=r"(r0), "=r"(r1), "=r"(r2), "=r"(r3) : "r"(addr))

#define MMA16816(d, a, b) \
    asm volatile("mma.sync.aligned.m16n8k16.row.col.f32.bf16.bf16.f32 " \
                 "{%0,%1,%2,%3}, {%4,%5,%6,%7}, {%8,%9}, {%0,%1,%2,%3};" \
                 : "+f"((d)[0]), "+f"((d)[1]), "+f"((d)[2]), "+f"((d)[3]) \
                 : "r"((a)[0]), "r"((a)[1]), "r"((a)[2]), "r"((a)[3]), \
                   "r"((b)[0]), "r"((b)[1]))

__device__ __forceinline__ void cpasync16(uint32_t daddr, const void* g) {
    asm volatile("cp.async.cg.shared.global [%0], [%1], 16;" :: "r"(daddr), "l"(g));
}

__device__ __forceinline__ void split2(float v, __nv_bfloat16& h, __nv_bfloat16& l) {
    h = __float2bfloat16(v);
    l = __float2bfloat16(v - __bfloat162float(h));
}

// ---------------- split kernels ---------------------------------------------
__global__ void __launch_bounds__(256)
xsplit_kernel(const float* __restrict__ x, __nv_bfloat16* __restrict__ hi,
              __nv_bfloat16* __restrict__ lo, int n)
{
    int i = blockIdx.x * 256 + threadIdx.x;
    if (i < n) {
        __nv_bfloat16 h, l;
        split2(x[i], h, l);
        hi[i] = h; lo[i] = l;
    }
}

// W [K,N] fp32 row-major -> hi/lo [N,K] bf16 (transposed, K-major)
__global__ void __launch_bounds__(256)
wsplitT_kernel(const float* __restrict__ W, __nv_bfloat16* __restrict__ hi,
               __nv_bfloat16* __restrict__ lo, int K, int N)
{
    __shared__ float t[32][33];
    const int k0 = blockIdx.y * 32, n0 = blockIdx.x * 32;
    const int tx = threadIdx.x, ty = threadIdx.y;  // 32 x 8
    for (int i = ty; i < 32; i += 8)
        t[i][tx] = W[(size_t)(k0 + i) * N + n0 + tx];
    __syncthreads();
    for (int i = ty; i < 32; i += 8) {
        float v = t[tx][i];
        __nv_bfloat16 h, l;
        split2(v, h, l);
        const size_t o = (size_t)(n0 + i) * K + k0 + tx;
        hi[o] = h; lo[o] = l;
    }
}

// ---------------- fused 3-term bf16 mma.sync GEMM, 128x256 tile -------------
// C[M,N] = Ahi@Bhi^T + Alo@Bhi^T + Ahi@Blo^T
// A: [M,K] K-major bf16 (hi/lo); B: [N,K] K-major bf16 (hi/lo).
// Tile 128(M) x 256(N), BK=64, 2-stage cp.async, 16 warps (4m x 4n), warp 32x64.
#define ATILE_B 16384          // 128 rows x 128B
#define BTILE_B 32768          // 256 rows x 128B
#define CH_B (2 * ATILE_B + 2 * BTILE_B)   // 96KB/stage
#define OFF_ALO ATILE_B
#define OFF_BHI (2 * ATILE_B)
#define OFF_BLO (2 * ATILE_B + BTILE_B)
#define STAGES 2
#define GSMEM (STAGES * CH_B)  // 192KB

__device__ __forceinline__ void load_chunk(const __nv_bfloat16* __restrict__ Ahi,
                                           const __nv_bfloat16* __restrict__ Alo,
                                           const __nv_bfloat16* __restrict__ Bhi,
                                           const __nv_bfloat16* __restrict__ Blo,
                                           int bm, int bn, int K, int k0,
                                           uint32_t sbuf, int tid)
{
    // A tiles: 1024 16B-chunks each; 512 threads -> 2 per thread per tile
#pragma unroll
    for (int t = 0; t < 2; t++) {
        const int u = tid + t * 512;             // 0..1023
        const int row = u >> 3, c = u & 7;
        const uint32_t off = sw128(row * 128 + c * 16);
        const size_t ga = (size_t)(bm + row) * K + k0 + c * 8;
        cpasync16(sbuf + off,           Ahi + ga);
        cpasync16(sbuf + OFF_ALO + off, Alo + ga);
    }
    // B tiles: 2048 16B-chunks each; 4 per thread per tile
#pragma unroll
    for (int t = 0; t < 4; t++) {
        const int u = tid + t * 512;             // 0..2047
        const int row = u >> 3, c = u & 7;
        const uint32_t off = sw128(row * 128 + c * 16);
        const size_t gb = (size_t)(bn + row) * K + k0 + c * 8;
        cpasync16(sbuf + OFF_BHI + off, Bhi + gb);
        cpasync16(sbuf + OFF_BLO + off, Blo + gb);
    }
}

template <int EPI, bool WF32, bool WSPL>
__global__ void __launch_bounds__(512, 1)
gemm_mma(const __nv_bfloat16* __restrict__ Ahi, const __nv_bfloat16* __restrict__ Alo,
         const __nv_bfloat16* __restrict__ Bhi, const __nv_bfloat16* __restrict__ Blo,
         float* __restrict__ C, const float* __restrict__ Rr,
         __nv_bfloat16* __restrict__ Chi, __nv_bfloat16* __restrict__ Clo,
         int N, int K)
{
    extern __shared__ char smem[];
    const uint32_t sb = smem_u32(smem);
    const int tid = threadIdx.x;
    const int wid = tid >> 5, lane = tid & 31;
    const int bm = blockIdx.y * 128, bn = blockIdx.x * 256;
    const int wm = (wid & 3) * 32;     // warp m offset (0..96)
    const int wn = (wid >> 2) * 64;    // warp n offset (0..192)

    const int nch = K >> 6;

    float acc[2][8][4];
#pragma unroll
    for (int mi = 0; mi < 2; mi++)
#pragma unroll
        for (int ni = 0; ni < 8; ni++)
#pragma unroll
            for (int j = 0; j < 4; j++) acc[mi][ni][j] = 0.f;

    // prologue
    load_chunk(Ahi, Alo, Bhi, Blo, bm, bn, K, 0, sb, tid);
    asm volatile("cp.async.commit_group;" ::: "memory");

    for (int c = 0; c < nch; c++) {
        if (c + 1 < nch) {
            load_chunk(Ahi, Alo, Bhi, Blo, bm, bn, K, (c + 1) * 64,
                       sb + ((c + 1) & 1) * CH_B, tid);
            asm volatile("cp.async.commit_group;" ::: "memory");
            asm volatile("cp.async.wait_group 1;" ::: "memory");
        } else {
            asm volatile("cp.async.wait_group 0;" ::: "memory");
        }
        __syncthreads();

        const uint32_t st = sb + (c & 1) * CH_B;
#pragma unroll
        for (int ks = 0; ks < 4; ks++) {
            const uint32_t cofs = ks * 32 + (lane >> 4) * 16;
            uint32_t ah[2][4], al[2][4];
#pragma unroll
            for (int mi = 0; mi < 2; mi++) {
                const uint32_t ro = sw128((wm + mi * 16 + (lane & 15)) * 128 + cofs);
                LDSM4(ah[mi][0], ah[mi][1], ah[mi][2], ah[mi][3], st + ro);
                LDSM4(al[mi][0], al[mi][1], al[mi][2], al[mi][3], st + OFF_ALO + ro);
            }
#pragma unroll
            for (int np = 0; np < 4; np++) {
                const uint32_t ro = sw128((wn + np * 16 + (lane & 15)) * 128 + cofs);
                uint32_t bh[2][2], bl[2][2];
                {
                    uint32_t r0, r1, r2, r3;
                    LDSM4(r0, r1, r2, r3, st + OFF_BHI + ro);
                    bh[0][0] = r0; bh[0][1] = r2;
                    bh[1][0] = r1; bh[1][1] = r3;
                    LDSM4(r0, r1, r2, r3, st + OFF_BLO + ro);
                    bl[0][0] = r0; bl[0][1] = r2;
                    bl[1][0] = r1; bl[1][1] = r3;
                }
                // term-major: 4 independent MMAs between same-acc updates
#pragma unroll
                for (int mi = 0; mi < 2; mi++)
#pragma unroll
                    for (int cc = 0; cc < 2; cc++)
                        MMA16816(acc[mi][np * 2 + cc], ah[mi], bh[cc]);
#pragma unroll
                for (int mi = 0; mi < 2; mi++)
#pragma unroll
                    for (int cc = 0; cc < 2; cc++)
                        MMA16816(acc[mi][np * 2 + cc], al[mi], bh[cc]);
#pragma unroll
                for (int mi = 0; mi < 2; mi++)
#pragma unroll
                    for (int cc = 0; cc < 2; cc++)
                        MMA16816(acc[mi][np * 2 + cc], ah[mi], bl[cc]);
            }
        }
        __syncthreads();
    }

    // epilogue
#pragma unroll
    for (int mi = 0; mi < 2; mi++) {
#pragma unroll
        for (int ni = 0; ni < 8; ni++) {
            const int row0 = bm + wm + mi * 16 + (lane >> 2);
            const int col  = bn + wn + ni * 8 + (lane & 3) * 2;
#pragma unroll
            for (int h = 0; h < 2; h++) {
                const size_t gofs = (size_t)(row0 + h * 8) * N + col;
                float2 v;
                v.x = acc[mi][ni][h * 2 + 0];
                v.y = acc[mi][ni][h * 2 + 1];
                if (EPI == 1) {
                    float2 rr = *(const float2*)(Rr + gofs);
                    v.x += rr.x; v.y += rr.y;
                } else if (EPI == 2) {
                    v.x = 0.5f * v.x * (1.f + erff(v.x * 0.70710678118654752f));
                    v.y = 0.5f * v.y * (1.f + erff(v.y * 0.70710678118654752f));
                }
                if (WF32) *(float2*)(C + gofs) = v;
                if (WSPL) {
                    __nv_bfloat16 h0, l0, h1, l1;
                    split2(v.x, h0, l0);
                    split2(v.y, h1, l1);
                    __nv_bfloat162 hh; hh.x = h0; hh.y = h1;
                    __nv_bfloat162 ll; ll.x = l0; ll.y = l1;
                    *(__nv_bfloat162*)(Chi + gofs) = hh;
                    *(__nv_bfloat162*)(Clo + gofs) = ll;
                }
            }
        }
    }
}

// ---------------- block-diagonal attention (fp32, writes bf16 hi/lo) -------
__global__ void __launch_bounds__(256)
attn_kernel(const float* __restrict__ qkv, __nv_bfloat16* __restrict__ atthi,
            __nv_bfloat16* __restrict__ attlo)
{
    __shared__ float s[NH][GRP][HD];

    const int grp  = blockIdx.x;
    const int w    = threadIdx.x >> 5;
    const int lane = threadIdx.x & 31;
    const size_t nodebase = (size_t)(grp * GRP + lane) * D_QKV + w * 96;

    {
        const float4* kr = (const float4*)(qkv + nodebase + 32);
        float4* sd = (float4*)&s[w][lane][0];
#pragma unroll
        for (int u = 0; u < 8; u++) sd[u] = kr[u];
    }
    float q[32];
    {
        const float4* qr = (const float4*)(qkv + nodebase);
#pragma unroll
        for (int u = 0; u < 8; u++) ((float4*)q)[u] = qr[u];
    }
    __syncwarp();

    float sc[32];
    for (int j = 0; j < 32; j++) {
        const float4* kr = (const float4*)&s[w][j][0];
        float a = 0.f;
#pragma unroll
        for (int u = 0; u < 8; u++) {
            float4 kv = kr[u];
            a = fmaf(q[u * 4 + 0], kv.x, a);
            a = fmaf(q[u * 4 + 1], kv.y, a);
            a = fmaf(q[u * 4 + 2], kv.z, a);
            a = fmaf(q[u * 4 + 3], kv.w, a);
        }
        sc[j] = a * 0.17677669529663687f;
    }

    float m = -1e30f;
#pragma unroll
    for (int j = 0; j < 32; j++) m = fmaxf(m, sc[j]);
    float sum = 0.f;
#pragma unroll
    for (int j = 0; j < 32; j++) { sc[j] = expf(sc[j] - m); sum += sc[j]; }
    const float inv = 1.0f / sum;

    __syncwarp();
    {
        const float4* vr = (const float4*)(qkv + nodebase + 64);
        float4* sd = (float4*)&s[w][lane][0];
#pragma unroll
        for (int u = 0; u < 8; u++) sd[u] = vr[u];
    }
    __syncwarp();

    const size_t obase = (size_t)(grp * GRP + lane) * D + w * HD;
#pragma unroll
    for (int u = 0; u < 8; u++) {
        float4 a = {0.f, 0.f, 0.f, 0.f};
        for (int j = 0; j < 32; j++) {
            float4 vv = ((const float4*)&s[w][j][0])[u];
            a.x = fmaf(sc[j], vv.x, a.x);
            a.y = fmaf(sc[j], vv.y, a.y);
            a.z = fmaf(sc[j], vv.z, a.z);
            a.w = fmaf(sc[j], vv.w, a.w);
        }
        a.x *= inv; a.y *= inv; a.z *= inv; a.w *= inv;
        __nv_bfloat16 h, l;
        split2(a.x, h, l); atthi[obase + u * 4 + 0] = h; attlo[obase + u * 4 + 0] = l;
        split2(a.y, h, l); atthi[obase + u * 4 + 1] = h; attlo[obase + u * 4 + 1] = l;
        split2(a.z, h, l); atthi[obase + u * 4 + 2] = h; attlo[obase + u * 4 + 2] = l;
        split2(a.w, h, l); atthi[obase + u * 4 + 3] = h; attlo[obase + u * 4 + 3] = l;
    }
}

// ---------------- LayerNorm: warp per row, D=256 ----------------------------
template <bool SPLIT>
__global__ void __launch_bounds__(256)
ln_kernel(const float* __restrict__ x, const float* __restrict__ g,
          const float* __restrict__ b, float* __restrict__ y,
          __nv_bfloat16* __restrict__ yhi, __nv_bfloat16* __restrict__ ylo)
{
    const int row  = blockIdx.x * 8 + (threadIdx.x >> 5);
    const int lane = threadIdx.x & 31;
    const float* xr = x + (size_t)row * D;

    float v[8];
    float sum = 0.f;
#pragma unroll
    for (int u = 0; u < 8; u++) { v[u] = xr[u * 32 + lane]; sum += v[u]; }
#pragma unroll
    for (int o = 16; o > 0; o >>= 1) sum += __shfl_xor_sync(0xffffffffu, sum, o);
    const float mean = sum * (1.0f / D);

    float vs = 0.f;
#pragma unroll
    for (int u = 0; u < 8; u++) { float d = v[u] - mean; vs = fmaf(d, d, vs); }
#pragma unroll
    for (int o = 16; o > 0; o >>= 1) vs += __shfl_xor_sync(0xffffffffu, vs, o);
    const float rstd = rsqrtf(vs * (1.0f / D) + LN_EPS);

    float* yr = y + (size_t)row * D;
#pragma unroll
    for (int u = 0; u < 8; u++) {
        const int c = u * 32 + lane;
        const float o = (v[u] - mean) * rstd * g[c] + b[c];
        yr[c] = o;
        if (SPLIT) {
            __nv_bfloat16 h, l;
            split2(o, h, l);
            yhi[(size_t)row * D + c] = h;
            ylo[(size_t)row * D + c] = l;
        }
    }
}

// ---------------- launch ----------------------------------------------------
extern "C" void kernel_launch(void* const* d_in, const int* in_sizes, int n_in,
                              void* d_out, int out_size)
{
    const float* x      = (const float*)d_in[0];
    const float* W_qkv  = (const float*)d_in[2];
    const float* W_o    = (const float*)d_in[3];
    const float* ln1_g  = (const float*)d_in[4];
    const float* ln1_b  = (const float*)d_in[5];
    const float* W_i    = (const float*)d_in[6];
    const float* W_out2 = (const float*)d_in[7];
    const float* ln2_g  = (const float*)d_in[8];
    const float* ln2_b  = (const float*)d_in[9];
    float* out = (float*)d_out;

    __nv_bfloat16 *Xhi, *Xlo, *atthi, *attlo, *prehi, *prelo, *interhi, *interlo;
    __nv_bfloat16 *Wqh, *Wql, *Woh, *Wol, *Wih, *Wil, *W2h, *W2l;
    float *qkv, *tmp1, *pre, *tmp2;
    cudaGetSymbolAddress((void**)&Xhi, g_Xhi);       cudaGetSymbolAddress((void**)&Xlo, g_Xlo);
    cudaGetSymbolAddress((void**)&qkv, g_qkv);
    cudaGetSymbolAddress((void**)&atthi, g_atthi);   cudaGetSymbolAddress((void**)&attlo, g_attlo);
    cudaGetSymbolAddress((void**)&tmp1, g_tmp1);
    cudaGetSymbolAddress((void**)&pre, g_pre);
    cudaGetSymbolAddress((void**)&prehi, g_prehi);   cudaGetSymbolAddress((void**)&prelo, g_prelo);
    cudaGetSymbolAddress((void**)&interhi, g_interhi); cudaGetSymbolAddress((void**)&interlo, g_interlo);
    cudaGetSymbolAddress((void**)&tmp2, g_tmp2);
    cudaGetSymbolAddress((void**)&Wqh, g_Wqkv_hi);   cudaGetSymbolAddress((void**)&Wql, g_Wqkv_lo);
    cudaGetSymbolAddress((void**)&Woh, g_Wo_hi);     cudaGetSymbolAddress((void**)&Wol, g_Wo_lo);
    cudaGetSymbolAddress((void**)&Wih, g_Wi_hi);     cudaGetSymbolAddress((void**)&Wil, g_Wi_lo);
    cudaGetSymbolAddress((void**)&W2h, g_W2_hi);     cudaGetSymbolAddress((void**)&W2l, g_W2_lo);

    cudaFuncSetAttribute(gemm_mma<0, true,  false>, cudaFuncAttributeMaxDynamicSharedMemorySize, GSMEM);
    cudaFuncSetAttribute(gemm_mma<1, true,  false>, cudaFuncAttributeMaxDynamicSharedMemorySize, GSMEM);
    cudaFuncSetAttribute(gemm_mma<2, false, true >, cudaFuncAttributeMaxDynamicSharedMemorySize, GSMEM);

    // 0) weight split+transpose
    wsplitT_kernel<<<dim3(D_QKV / 32, D / 32), dim3(32, 8)>>>(W_qkv,  Wqh, Wql, D,  D_QKV);
    wsplitT_kernel<<<dim3(D / 32,     D / 32), dim3(32, 8)>>>(W_o,    Woh, Wol, D,  D);
    wsplitT_kernel<<<dim3(DI / 32,    D / 32), dim3(32, 8)>>>(W_i,    Wih, Wil, D,  DI);
    wsplitT_kernel<<<dim3(D / 32,    DI / 32), dim3(32, 8)>>>(W_out2, W2h, W2l, DI, D);
    // 0b) X split
    xsplit_kernel<<<NV * D / 256, 256>>>(x, Xhi, Xlo, NV * D);

    // 1) qkv = X @ W_qkv                         [16384, 768]
    gemm_mma<0, true, false><<<dim3(D_QKV / 256, NV / 128), 512, GSMEM>>>(
        Xhi, Xlo, Wqh, Wql, qkv, nullptr, nullptr, nullptr, D_QKV, D);
    // 2) attention -> att (bf16 hi/lo)
    attn_kernel<<<NGROUPS, 256>>>(qkv, atthi, attlo);
    // 3) tmp1 = att @ W_o + X
    gemm_mma<1, true, false><<<dim3(D / 256, NV / 128), 512, GSMEM>>>(
        atthi, attlo, Woh, Wol, tmp1, x, nullptr, nullptr, D, D);
    // 4) pre = LN1(tmp1)  (+ bf16 split)
    ln_kernel<true><<<NV / 8, 256>>>(tmp1, ln1_g, ln1_b, pre, prehi, prelo);
    // 5) inter = gelu(pre @ W_i)  -> bf16 hi/lo only
    gemm_mma<2, false, true><<<dim3(DI / 256, NV / 128), 512, GSMEM>>>(
        prehi, prelo, Wih, Wil, nullptr, nullptr, interhi, interlo, DI, D);
    // 6) tmp2 = inter @ W_out2 + pre
    gemm_mma<1, true, false><<<dim3(D / 256, NV / 128), 512, GSMEM>>>(
        interhi, interlo, W2h, W2l, tmp2, pre, nullptr, nullptr, D, DI);
    // 7) out = LN2(tmp2)
    ln_kernel<false><<<NV / 8, 256>>>(tmp2, ln2_g, ln2_b, out, nullptr, nullptr);
}

// round 7
// speedup vs baseline: 1.5015x; 1.5015x over previous
#include <cuda_runtime.h>
#include <cuda_fp16.h>
#include <math.h>
#include <stdint.h>

// Problem constants (fixed by setup_inputs)
#define NV 16384
#define GRP 32
#define NGROUPS 512
#define D 256
#define NH 8
#define HD 32
#define DI 1024
#define D_QKV 768
#define LN_EPS 1e-12f

// ---------------- scratch (device globals; no allocation allowed) ----------
__device__ __half g_X16[NV * D];
__device__ float  g_qkv[NV * D_QKV];
__device__ __half g_att16[NV * D];
__device__ float  g_tmp1[NV * D];
__device__ float  g_pre[NV * D];
__device__ __half g_pre16[NV * D];
__device__ __half g_inter16[NV * DI];
__device__ float  g_tmp2[NV * D];
__device__ __half g_Wqkv_hi[D_QKV * D], g_Wqkv_lo[D_QKV * D];
__device__ __half g_Wo_hi[D * D],       g_Wo_lo[D * D];
__device__ __half g_Wi_hi[DI * D],      g_Wi_lo[DI * D];
__device__ __half g_W2_hi[D * DI],      g_W2_lo[D * DI];

// ---------------- helpers ---------------------------------------------------
__device__ __forceinline__ uint32_t smem_u32(const void* p) {
    uint32_t a;
    asm("{ .reg .u64 t; cvta.to.shared.u64 t, %1; cvt.u32.u64 %0, t; }" : "=r"(a) : "l"(p));
    return a;
}
__device__ __forceinline__ uint32_t sw128(uint32_t x) { return x ^ ((x >> 3) & 0x70); }

#define LDSM4(r0, r1, r2, r3, addr) \
    asm volatile("ldmatrix.sync.aligned.m8n8.x4.shared.b16 {%0,%1,%2,%3}, [%4];" \
                 : "=r"(r0), "=r"(r1), "=r"(r2), "=r"(r3) : "r"(addr))

#define MMA16816(d, a, b) \
    asm volatile("mma.sync.aligned.m16n8k16.row.col.f32.f16.f16.f32 " \
                 "{%0,%1,%2,%3}, {%4,%5,%6,%7}, {%8,%9}, {%0,%1,%2,%3};" \
                 : "+f"((d)[0]), "+f"((d)[1]), "+f"((d)[2]), "+f"((d)[3]) \
                 : "r"((a)[0]), "r"((a)[1]), "r"((a)[2]), "r"((a)[3]), \
                   "r"((b)[0]), "r"((b)[1]))

__device__ __forceinline__ void cpasync16(uint32_t daddr, const void* g) {
    asm volatile("cp.async.cg.shared.global [%0], [%1], 16;" :: "r"(daddr), "l"(g));
}

__device__ __forceinline__ void wsplit2(float v, __half& h, __half& l) {
    h = __float2half_rn(v);
    l = __float2half_rn(v - __half2float(h));
}

// ---------------- conversion kernels ----------------------------------------
__global__ void __launch_bounds__(256)
x16_kernel(const float* __restrict__ x, __half* __restrict__ y, int n)
{
    int i = blockIdx.x * 256 + threadIdx.x;
    if (i < n) y[i] = __float2half_rn(x[i]);
}

// W [K,N] fp32 row-major -> hi/lo [N,K] fp16 (transposed, K-major)
__global__ void __launch_bounds__(256)
wsplitT_kernel(const float* __restrict__ W, __half* __restrict__ hi,
               __half* __restrict__ lo, int K, int N)
{
    __shared__ float t[32][33];
    const int k0 = blockIdx.y * 32, n0 = blockIdx.x * 32;
    const int tx = threadIdx.x, ty = threadIdx.y;  // 32 x 8
    for (int i = ty; i < 32; i += 8)
        t[i][tx] = W[(size_t)(k0 + i) * N + n0 + tx];
    __syncthreads();
    for (int i = ty; i < 32; i += 8) {
        float v = t[tx][i];
        __half h, l;
        wsplit2(v, h, l);
        const size_t o = (size_t)(n0 + i) * K + k0 + tx;
        hi[o] = h; lo[o] = l;
    }
}

// ---------------- 2-term fp16 mma.sync GEMM ---------------------------------
// C[M,N] = A16@Whi^T + A16@Wlo^T
// A: [M,K] K-major fp16; W: [N,K] K-major fp16 (hi/lo).
// Tile 128x128, BK=64, 2-stage cp.async, 8 warps (4m x 2n), warp 32x64.
#define TILE_B 16384                  // 128 rows x 128B
#define CH_B   (3 * TILE_B)           // A | Whi | Wlo = 48KB/stage
#define OFF_BH TILE_B
#define OFF_BL (2 * TILE_B)
#define GSMEM  (2 * CH_B)             // 96KB

__device__ __forceinline__ void load_chunk(const __half* __restrict__ A,
                                           const __half* __restrict__ Bh,
                                           const __half* __restrict__ Bl,
                                           int bm, int bn, int K, int k0,
                                           uint32_t sbuf, int tid)
{
#pragma unroll
    for (int t = 0; t < 4; t++) {
        const int u = tid + t * 256;             // 0..1023
        const int row = u >> 3, c = u & 7;
        const uint32_t off = sw128(row * 128 + c * 16);
        const size_t ga = (size_t)(bm + row) * K + k0 + c * 8;
        const size_t gb = (size_t)(bn + row) * K + k0 + c * 8;
        cpasync16(sbuf + off,          A  + ga);
        cpasync16(sbuf + OFF_BH + off, Bh + gb);
        cpasync16(sbuf + OFF_BL + off, Bl + gb);
    }
}

template <int EPI, bool WF32, bool W16>
__global__ void __launch_bounds__(256, 1)
gemm_mma(const __half* __restrict__ A16,
         const __half* __restrict__ Whi, const __half* __restrict__ Wlo,
         float* __restrict__ C, const float* __restrict__ Rr,
         __half* __restrict__ C16,
         int N, int K)
{
    extern __shared__ char smem[];
    const uint32_t sb = smem_u32(smem);
    const int tid = threadIdx.x;
    const int wid = tid >> 5, lane = tid & 31;
    const int bm = blockIdx.y * 128, bn = blockIdx.x * 128;
    const int wm = (wid & 3) * 32;     // warp m offset
    const int wn = (wid >> 2) * 64;    // warp n offset

    const int nch = K >> 6;

    float acc[2][8][4];
#pragma unroll
    for (int mi = 0; mi < 2; mi++)
#pragma unroll
        for (int ni = 0; ni < 8; ni++)
#pragma unroll
            for (int j = 0; j < 4; j++) acc[mi][ni][j] = 0.f;

    load_chunk(A16, Whi, Wlo, bm, bn, K, 0, sb, tid);
    asm volatile("cp.async.commit_group;" ::: "memory");

    for (int c = 0; c < nch; c++) {
        if (c + 1 < nch) {
            load_chunk(A16, Whi, Wlo, bm, bn, K, (c + 1) * 64,
                       sb + ((c + 1) & 1) * CH_B, tid);
            asm volatile("cp.async.commit_group;" ::: "memory");
            asm volatile("cp.async.wait_group 1;" ::: "memory");
        } else {
            asm volatile("cp.async.wait_group 0;" ::: "memory");
        }
        __syncthreads();

        const uint32_t st = sb + (c & 1) * CH_B;
#pragma unroll
        for (int ks = 0; ks < 4; ks++) {
            const uint32_t cofs = ks * 32 + (lane >> 4) * 16;
            uint32_t a[2][4];
#pragma unroll
            for (int mi = 0; mi < 2; mi++) {
                const uint32_t ro = sw128((wm + mi * 16 + (lane & 15)) * 128 + cofs);
                LDSM4(a[mi][0], a[mi][1], a[mi][2], a[mi][3], st + ro);
            }
            uint32_t bh[8][2], bl[8][2];
#pragma unroll
            for (int np = 0; np < 4; np++) {
                const uint32_t ro = sw128((wn + np * 16 + (lane & 15)) * 128 + cofs);
                uint32_t r0, r1, r2, r3;
                LDSM4(r0, r1, r2, r3, st + OFF_BH + ro);
                bh[np * 2][0] = r0; bh[np * 2][1] = r2;
                bh[np * 2 + 1][0] = r1; bh[np * 2 + 1][1] = r3;
                LDSM4(r0, r1, r2, r3, st + OFF_BL + ro);
                bl[np * 2][0] = r0; bl[np * 2][1] = r2;
                bl[np * 2 + 1][0] = r1; bl[np * 2 + 1][1] = r3;
            }
            // term-major: 16 independent MMAs between same-acc updates
#pragma unroll
            for (int mi = 0; mi < 2; mi++)
#pragma unroll
                for (int ni = 0; ni < 8; ni++)
                    MMA16816(acc[mi][ni], a[mi], bh[ni]);
#pragma unroll
            for (int mi = 0; mi < 2; mi++)
#pragma unroll
                for (int ni = 0; ni < 8; ni++)
                    MMA16816(acc[mi][ni], a[mi], bl[ni]);
        }
        __syncthreads();
    }

    // epilogue
#pragma unroll
    for (int mi = 0; mi < 2; mi++) {
#pragma unroll
        for (int ni = 0; ni < 8; ni++) {
            const int row0 = bm + wm + mi * 16 + (lane >> 2);
            const int col  = bn + wn + ni * 8 + (lane & 3) * 2;
#pragma unroll
            for (int h = 0; h < 2; h++) {
                const size_t gofs = (size_t)(row0 + h * 8) * N + col;
                float2 v;
                v.x = acc[mi][ni][h * 2 + 0];
                v.y = acc[mi][ni][h * 2 + 1];
                if (EPI == 1) {
                    float2 rr = *(const float2*)(Rr + gofs);
                    v.x += rr.x; v.y += rr.y;
                } else if (EPI == 2) {
                    v.x = 0.5f * v.x * (1.f + erff(v.x * 0.70710678118654752f));
                    v.y = 0.5f * v.y * (1.f + erff(v.y * 0.70710678118654752f));
                }
                if (WF32) *(float2*)(C + gofs) = v;
                if (W16) {
                    __half2 hh;
                    hh.x = __float2half_rn(v.x);
                    hh.y = __float2half_rn(v.y);
                    *(__half2*)(C16 + gofs) = hh;
                }
            }
        }
    }
}

// ---------------- block-diagonal attention (fp32 in, fp16 out) -------------
__global__ void __launch_bounds__(256)
attn_kernel(const float* __restrict__ qkv, __half* __restrict__ att16)
{
    __shared__ float s[NH][GRP][HD];

    const int grp  = blockIdx.x;
    const int w    = threadIdx.x >> 5;
    const int lane = threadIdx.x & 31;
    const size_t nodebase = (size_t)(grp * GRP + lane) * D_QKV + w * 96;

    {
        const float4* kr = (const float4*)(qkv + nodebase + 32);
        float4* sd = (float4*)&s[w][lane][0];
#pragma unroll
        for (int u = 0; u < 8; u++) sd[u] = kr[u];
    }
    float q[32];
    {
        const float4* qr = (const float4*)(qkv + nodebase);
#pragma unroll
        for (int u = 0; u < 8; u++) ((float4*)q)[u] = qr[u];
    }
    __syncwarp();

    float sc[32];
    for (int j = 0; j < 32; j++) {
        const float4* kr = (const float4*)&s[w][j][0];
        float a = 0.f;
#pragma unroll
        for (int u = 0; u < 8; u++) {
            float4 kv = kr[u];
            a = fmaf(q[u * 4 + 0], kv.x, a);
            a = fmaf(q[u * 4 + 1], kv.y, a);
            a = fmaf(q[u * 4 + 2], kv.z, a);
            a = fmaf(q[u * 4 + 3], kv.w, a);
        }
        sc[j] = a * 0.17677669529663687f;
    }

    float m = -1e30f;
#pragma unroll
    for (int j = 0; j < 32; j++) m = fmaxf(m, sc[j]);
    float sum = 0.f;
#pragma unroll
    for (int j = 0; j < 32; j++) { sc[j] = expf(sc[j] - m); sum += sc[j]; }
    const float inv = 1.0f / sum;

    __syncwarp();
    {
        const float4* vr = (const float4*)(qkv + nodebase + 64);
        float4* sd = (float4*)&s[w][lane][0];
#pragma unroll
        for (int u = 0; u < 8; u++) sd[u] = vr[u];
    }
    __syncwarp();

    const size_t obase = (size_t)(grp * GRP + lane) * D + w * HD;
#pragma unroll
    for (int u = 0; u < 8; u++) {
        float4 a = {0.f, 0.f, 0.f, 0.f};
        for (int j = 0; j < 32; j++) {
            float4 vv = ((const float4*)&s[w][j][0])[u];
            a.x = fmaf(sc[j], vv.x, a.x);
            a.y = fmaf(sc[j], vv.y, a.y);
            a.z = fmaf(sc[j], vv.z, a.z);
            a.w = fmaf(sc[j], vv.w, a.w);
        }
        __half2 h0, h1;
        h0.x = __float2half_rn(a.x * inv); h0.y = __float2half_rn(a.y * inv);
        h1.x = __float2half_rn(a.z * inv); h1.y = __float2half_rn(a.w * inv);
        *(__half2*)(att16 + obase + u * 4)     = h0;
        *(__half2*)(att16 + obase + u * 4 + 2) = h1;
    }
}

// ---------------- LayerNorm: warp per row, D=256 ----------------------------
template <bool H16>
__global__ void __launch_bounds__(256)
ln_kernel(const float* __restrict__ x, const float* __restrict__ g,
          const float* __restrict__ b, float* __restrict__ y,
          __half* __restrict__ y16)
{
    const int row  = blockIdx.x * 8 + (threadIdx.x >> 5);
    const int lane = threadIdx.x & 31;
    const float* xr = x + (size_t)row * D;

    float v[8];
    float sum = 0.f;
#pragma unroll
    for (int u = 0; u < 8; u++) { v[u] = xr[u * 32 + lane]; sum += v[u]; }
#pragma unroll
    for (int o = 16; o > 0; o >>= 1) sum += __shfl_xor_sync(0xffffffffu, sum, o);
    const float mean = sum * (1.0f / D);

    float vs = 0.f;
#pragma unroll
    for (int u = 0; u < 8; u++) { float d = v[u] - mean; vs = fmaf(d, d, vs); }
#pragma unroll
    for (int o = 16; o > 0; o >>= 1) vs += __shfl_xor_sync(0xffffffffu, vs, o);
    const float rstd = rsqrtf(vs * (1.0f / D) + LN_EPS);

    float* yr = y + (size_t)row * D;
#pragma unroll
    for (int u = 0; u < 8; u++) {
        const int c = u * 32 + lane;
        const float o = (v[u] - mean) * rstd * g[c] + b[c];
        yr[c] = o;
        if (H16) y16[(size_t)row * D + c] = __float2half_rn(o);
    }
}

// ---------------- launch ----------------------------------------------------
extern "C" void kernel_launch(void* const* d_in, const int* in_sizes, int n_in,
                              void* d_out, int out_size)
{
    const float* x      = (const float*)d_in[0];
    const float* W_qkv  = (const float*)d_in[2];
    const float* W_o    = (const float*)d_in[3];
    const float* ln1_g  = (const float*)d_in[4];
    const float* ln1_b  = (const float*)d_in[5];
    const float* W_i    = (const float*)d_in[6];
    const float* W_out2 = (const float*)d_in[7];
    const float* ln2_g  = (const float*)d_in[8];
    const float* ln2_b  = (const float*)d_in[9];
    float* out = (float*)d_out;

    __half *X16, *att16, *pre16, *inter16;
    __half *Wqh, *Wql, *Woh, *Wol, *Wih, *Wil, *W2h, *W2l;
    float *qkv, *tmp1, *pre, *tmp2;
    cudaGetSymbolAddress((void**)&X16, g_X16);
    cudaGetSymbolAddress((void**)&qkv, g_qkv);
    cudaGetSymbolAddress((void**)&att16, g_att16);
    cudaGetSymbolAddress((void**)&tmp1, g_tmp1);
    cudaGetSymbolAddress((void**)&pre, g_pre);
    cudaGetSymbolAddress((void**)&pre16, g_pre16);
    cudaGetSymbolAddress((void**)&inter16, g_inter16);
    cudaGetSymbolAddress((void**)&tmp2, g_tmp2);
    cudaGetSymbolAddress((void**)&Wqh, g_Wqkv_hi);   cudaGetSymbolAddress((void**)&Wql, g_Wqkv_lo);
    cudaGetSymbolAddress((void**)&Woh, g_Wo_hi);     cudaGetSymbolAddress((void**)&Wol, g_Wo_lo);
    cudaGetSymbolAddress((void**)&Wih, g_Wi_hi);     cudaGetSymbolAddress((void**)&Wil, g_Wi_lo);
    cudaGetSymbolAddress((void**)&W2h, g_W2_hi);     cudaGetSymbolAddress((void**)&W2l, g_W2_lo);

    cudaFuncSetAttribute(gemm_mma<0, true,  false>, cudaFuncAttributeMaxDynamicSharedMemorySize, GSMEM);
    cudaFuncSetAttribute(gemm_mma<1, true,  false>, cudaFuncAttributeMaxDynamicSharedMemorySize, GSMEM);
    cudaFuncSetAttribute(gemm_mma<2, false, true >, cudaFuncAttributeMaxDynamicSharedMemorySize, GSMEM);

    // 0) weight split+transpose; X conversion
    wsplitT_kernel<<<dim3(D_QKV / 32, D / 32), dim3(32, 8)>>>(W_qkv,  Wqh, Wql, D,  D_QKV);
    wsplitT_kernel<<<dim3(D / 32,     D / 32), dim3(32, 8)>>>(W_o,    Woh, Wol, D,  D);
    wsplitT_kernel<<<dim3(DI / 32,    D / 32), dim3(32, 8)>>>(W_i,    Wih, Wil, D,  DI);
    wsplitT_kernel<<<dim3(D / 32,    DI / 32), dim3(32, 8)>>>(W_out2, W2h, W2l, DI, D);
    x16_kernel<<<NV * D / 256, 256>>>(x, X16, NV * D);

    // 1) qkv = X @ W_qkv                         [16384, 768]
    gemm_mma<0, true, false><<<dim3(D_QKV / 128, NV / 128), 256, GSMEM>>>(
        X16, Wqh, Wql, qkv, nullptr, nullptr, D_QKV, D);
    // 2) attention -> att (fp16)
    attn_kernel<<<NGROUPS, 256>>>(qkv, att16);
    // 3) tmp1 = att @ W_o + X
    gemm_mma<1, true, false><<<dim3(D / 128, NV / 128), 256, GSMEM>>>(
        att16, Woh, Wol, tmp1, x, nullptr, D, D);
    // 4) pre = LN1(tmp1)  (+ fp16 copy)
    ln_kernel<true><<<NV / 8, 256>>>(tmp1, ln1_g, ln1_b, pre, pre16);
    // 5) inter = gelu(pre @ W_i)  -> fp16 only
    gemm_mma<2, false, true><<<dim3(DI / 128, NV / 128), 256, GSMEM>>>(
        pre16, Wih, Wil, nullptr, nullptr, inter16, DI, D);
    // 6) tmp2 = inter @ W_out2 + pre
    gemm_mma<1, true, false><<<dim3(D / 128, NV / 128), 256, GSMEM>>>(
        inter16, W2h, W2l, tmp2, pre, nullptr, D, DI);
    // 7) out = LN2(tmp2)
    ln_kernel<false><<<NV / 8, 256>>>(tmp2, ln2_g, ln2_b, out, nullptr);
}

// round 8
// speedup vs baseline: 1.8834x; 1.2543x over previous
#include <cuda_runtime.h>
#include <cuda_fp16.h>
#include <math.h>
#include <stdint.h>

// Problem constants (fixed by setup_inputs)
#define NV 16384
#define GRP 32
#define NGROUPS 512
#define D 256
#define NH 8
#define HD 32
#define DI 1024
#define D_QKV 768
#define LN_EPS 1e-12f

// ---------------- scratch (device globals; no allocation allowed) ----------
__device__ __half g_X16[NV * D];
__device__ float  g_qkv[NV * D_QKV];
__device__ __half g_att16[NV * D];
__device__ float  g_tmp1[NV * D];
__device__ float  g_pre[NV * D];
__device__ __half g_pre16[NV * D];
__device__ __half g_inter16[NV * DI];
__device__ float  g_tmp2[NV * D];
__device__ __half g_Wqkv16[D_QKV * D];
__device__ __half g_Wo16[D * D];
__device__ __half g_Wi16[DI * D];
__device__ __half g_W216[D * DI];

// ---------------- helpers ---------------------------------------------------
__device__ __forceinline__ uint32_t smem_u32(const void* p) {
    uint32_t a;
    asm("{ .reg .u64 t; cvta.to.shared.u64 t, %1; cvt.u32.u64 %0, t; }" : "=r"(a) : "l"(p));
    return a;
}
__device__ __forceinline__ uint32_t sw128(uint32_t x) { return x ^ ((x >> 3) & 0x70); }

#define LDSM4(r0, r1, r2, r3, addr) \
    asm volatile("ldmatrix.sync.aligned.m8n8.x4.shared.b16 {%0,%1,%2,%3}, [%4];" \
                 : "=r"(r0), "=r"(r1), "=r"(r2), "=r"(r3) : "r"(addr))

#define MMA16816(d, a, b) \
    asm volatile("mma.sync.aligned.m16n8k16.row.col.f32.f16.f16.f32 " \
                 "{%0,%1,%2,%3}, {%4,%5,%6,%7}, {%8,%9}, {%0,%1,%2,%3};" \
                 : "+f"((d)[0]), "+f"((d)[1]), "+f"((d)[2]), "+f"((d)[3]) \
                 : "r"((a)[0]), "r"((a)[1]), "r"((a)[2]), "r"((a)[3]), \
                   "r"((b)[0]), "r"((b)[1]))

__device__ __forceinline__ void cpasync16(uint32_t daddr, const void* g) {
    asm volatile("cp.async.cg.shared.global [%0], [%1], 16;" :: "r"(daddr), "l"(g));
}

// ---------------- conversion kernels ----------------------------------------
__global__ void __launch_bounds__(256)
x16_kernel(const float* __restrict__ x, __half* __restrict__ y, int n)
{
    int i = blockIdx.x * 256 + threadIdx.x;
    if (i < n) y[i] = __float2half_rn(x[i]);
}

// W [K,N] fp32 row-major -> [N,K] fp16 (transposed, K-major)
__global__ void __launch_bounds__(256)
wT16_kernel(const float* __restrict__ W, __half* __restrict__ o, int K, int N)
{
    __shared__ float t[32][33];
    const int k0 = blockIdx.y * 32, n0 = blockIdx.x * 32;
    const int tx = threadIdx.x, ty = threadIdx.y;  // 32 x 8
    for (int i = ty; i < 32; i += 8)
        t[i][tx] = W[(size_t)(k0 + i) * N + n0 + tx];
    __syncthreads();
    for (int i = ty; i < 32; i += 8)
        o[(size_t)(n0 + i) * K + k0 + tx] = __float2half_rn(t[tx][i]);
}

// ---------------- fp16 mma.sync GEMM ----------------------------------------
// C[M,N] = A16 @ W16^T.  A: [M,K] K-major; W: [N,K] K-major.
// Tile 128x128, BK=64, 3-stage cp.async, 8 warps (4m x 2n), warp 32x64.
#define TILE_B 16384                  // 128 rows x 128B
#define CH_B   (2 * TILE_B)           // A | W = 32KB/stage
#define OFF_BW TILE_B
#define STAGES 3
#define GSMEM  (STAGES * CH_B)        // 96KB

__device__ __forceinline__ void load_chunk(const __half* __restrict__ A,
                                           const __half* __restrict__ B,
                                           int bm, int bn, int K, int k0,
                                           uint32_t sbuf, int tid)
{
#pragma unroll
    for (int t = 0; t < 4; t++) {
        const int u = tid + t * 256;             // 0..1023
        const int row = u >> 3, c = u & 7;
        const uint32_t off = sw128(row * 128 + c * 16);
        cpasync16(sbuf + off,          A + (size_t)(bm + row) * K + k0 + c * 8);
        cpasync16(sbuf + OFF_BW + off, B + (size_t)(bn + row) * K + k0 + c * 8);
    }
}

template <int EPI, bool WF32, bool W16>
__global__ void __launch_bounds__(256, 1)
gemm_mma(const __half* __restrict__ A16, const __half* __restrict__ W,
         float* __restrict__ C, const float* __restrict__ Rr,
         __half* __restrict__ C16,
         int N, int K)
{
    extern __shared__ char smem[];
    const uint32_t sb = smem_u32(smem);
    const int tid = threadIdx.x;
    const int wid = tid >> 5, lane = tid & 31;
    const int bm = blockIdx.y * 128, bn = blockIdx.x * 128;
    const int wm = (wid & 3) * 32;     // warp m offset
    const int wn = (wid >> 2) * 64;    // warp n offset

    const int nch = K >> 6;

    float acc[2][8][4];
#pragma unroll
    for (int mi = 0; mi < 2; mi++)
#pragma unroll
        for (int ni = 0; ni < 8; ni++)
#pragma unroll
            for (int j = 0; j < 4; j++) acc[mi][ni][j] = 0.f;

    load_chunk(A16, W, bm, bn, K, 0, sb, tid);
    asm volatile("cp.async.commit_group;" ::: "memory");
    if (nch > 1) {
        load_chunk(A16, W, bm, bn, K, 64, sb + CH_B, tid);
    }
    asm volatile("cp.async.commit_group;" ::: "memory");

    for (int c = 0; c < nch; c++) {
        asm volatile("cp.async.wait_group 1;" ::: "memory");
        __syncthreads();
        if (c + 2 < nch) {
            load_chunk(A16, W, bm, bn, K, (c + 2) * 64,
                       sb + ((c + 2) % STAGES) * CH_B, tid);
        }
        asm volatile("cp.async.commit_group;" ::: "memory");

        const uint32_t st = sb + (c % STAGES) * CH_B;
#pragma unroll
        for (int ks = 0; ks < 4; ks++) {
            const uint32_t cofs = ks * 32 + (lane >> 4) * 16;
            uint32_t a[2][4];
#pragma unroll
            for (int mi = 0; mi < 2; mi++) {
                const uint32_t ro = sw128((wm + mi * 16 + (lane & 15)) * 128 + cofs);
                LDSM4(a[mi][0], a[mi][1], a[mi][2], a[mi][3], st + ro);
            }
            uint32_t b[8][2];
#pragma unroll
            for (int np = 0; np < 4; np++) {
                const uint32_t ro = sw128((wn + np * 16 + (lane & 15)) * 128 + cofs);
                uint32_t r0, r1, r2, r3;
                LDSM4(r0, r1, r2, r3, st + OFF_BW + ro);
                b[np * 2][0] = r0; b[np * 2][1] = r2;
                b[np * 2 + 1][0] = r1; b[np * 2 + 1][1] = r3;
            }
#pragma unroll
            for (int mi = 0; mi < 2; mi++)
#pragma unroll
                for (int ni = 0; ni < 8; ni++)
                    MMA16816(acc[mi][ni], a[mi], b[ni]);
        }
        __syncthreads();
    }

    // epilogue
#pragma unroll
    for (int mi = 0; mi < 2; mi++) {
#pragma unroll
        for (int ni = 0; ni < 8; ni++) {
            const int row0 = bm + wm + mi * 16 + (lane >> 2);
            const int col  = bn + wn + ni * 8 + (lane & 3) * 2;
#pragma unroll
            for (int h = 0; h < 2; h++) {
                const size_t gofs = (size_t)(row0 + h * 8) * N + col;
                float2 v;
                v.x = acc[mi][ni][h * 2 + 0];
                v.y = acc[mi][ni][h * 2 + 1];
                if (EPI == 1) {
                    float2 rr = *(const float2*)(Rr + gofs);
                    v.x += rr.x; v.y += rr.y;
                } else if (EPI == 2) {
                    v.x = 0.5f * v.x * (1.f + erff(v.x * 0.70710678118654752f));
                    v.y = 0.5f * v.y * (1.f + erff(v.y * 0.70710678118654752f));
                }
                if (WF32) *(float2*)(C + gofs) = v;
                if (W16) {
                    __half2 hh;
                    hh.x = __float2half_rn(v.x);
                    hh.y = __float2half_rn(v.y);
                    *(__half2*)(C16 + gofs) = hh;
                }
            }
        }
    }
}

// ---------------- block-diagonal attention (fp32 in, fp16 out) -------------
__global__ void __launch_bounds__(256)
attn_kernel(const float* __restrict__ qkv, __half* __restrict__ att16)
{
    __shared__ float s[NH][GRP][HD];

    const int grp  = blockIdx.x;
    const int w    = threadIdx.x >> 5;
    const int lane = threadIdx.x & 31;
    const size_t nodebase = (size_t)(grp * GRP + lane) * D_QKV + w * 96;

    {
        const float4* kr = (const float4*)(qkv + nodebase + 32);
        float4* sd = (float4*)&s[w][lane][0];
#pragma unroll
        for (int u = 0; u < 8; u++) sd[u] = kr[u];
    }
    float q[32];
    {
        const float4* qr = (const float4*)(qkv + nodebase);
#pragma unroll
        for (int u = 0; u < 8; u++) ((float4*)q)[u] = qr[u];
    }
    __syncwarp();

    float sc[32];
    for (int j = 0; j < 32; j++) {
        const float4* kr = (const float4*)&s[w][j][0];
        float a = 0.f;
#pragma unroll
        for (int u = 0; u < 8; u++) {
            float4 kv = kr[u];
            a = fmaf(q[u * 4 + 0], kv.x, a);
            a = fmaf(q[u * 4 + 1], kv.y, a);
            a = fmaf(q[u * 4 + 2], kv.z, a);
            a = fmaf(q[u * 4 + 3], kv.w, a);
        }
        sc[j] = a * 0.17677669529663687f;
    }

    float m = -1e30f;
#pragma unroll
    for (int j = 0; j < 32; j++) m = fmaxf(m, sc[j]);
    float sum = 0.f;
#pragma unroll
    for (int j = 0; j < 32; j++) { sc[j] = expf(sc[j] - m); sum += sc[j]; }
    const float inv = 1.0f / sum;

    __syncwarp();
    {
        const float4* vr = (const float4*)(qkv + nodebase + 64);
        float4* sd = (float4*)&s[w][lane][0];
#pragma unroll
        for (int u = 0; u < 8; u++) sd[u] = vr[u];
    }
    __syncwarp();

    const size_t obase = (size_t)(grp * GRP + lane) * D + w * HD;
#pragma unroll
    for (int u = 0; u < 8; u++) {
        float4 a = {0.f, 0.f, 0.f, 0.f};
        for (int j = 0; j < 32; j++) {
            float4 vv = ((const float4*)&s[w][j][0])[u];
            a.x = fmaf(sc[j], vv.x, a.x);
            a.y = fmaf(sc[j], vv.y, a.y);
            a.z = fmaf(sc[j], vv.z, a.z);
            a.w = fmaf(sc[j], vv.w, a.w);
        }
        __half2 h0, h1;
        h0.x = __float2half_rn(a.x * inv); h0.y = __float2half_rn(a.y * inv);
        h1.x = __float2half_rn(a.z * inv); h1.y = __float2half_rn(a.w * inv);
        *(__half2*)(att16 + obase + u * 4)     = h0;
        *(__half2*)(att16 + obase + u * 4 + 2) = h1;
    }
}

// ---------------- LayerNorm: warp per row, D=256 ----------------------------
template <bool H16>
__global__ void __launch_bounds__(256)
ln_kernel(const float* __restrict__ x, const float* __restrict__ g,
          const float* __restrict__ b, float* __restrict__ y,
          __half* __restrict__ y16)
{
    const int row  = blockIdx.x * 8 + (threadIdx.x >> 5);
    const int lane = threadIdx.x & 31;
    const float* xr = x + (size_t)row * D;

    float v[8];
    float sum = 0.f;
#pragma unroll
    for (int u = 0; u < 8; u++) { v[u] = xr[u * 32 + lane]; sum += v[u]; }
#pragma unroll
    for (int o = 16; o > 0; o >>= 1) sum += __shfl_xor_sync(0xffffffffu, sum, o);
    const float mean = sum * (1.0f / D);

    float vs = 0.f;
#pragma unroll
    for (int u = 0; u < 8; u++) { float d = v[u] - mean; vs = fmaf(d, d, vs); }
#pragma unroll
    for (int o = 16; o > 0; o >>= 1) vs += __shfl_xor_sync(0xffffffffu, vs, o);
    const float rstd = rsqrtf(vs * (1.0f / D) + LN_EPS);

    float* yr = y + (size_t)row * D;
#pragma unroll
    for (int u = 0; u < 8; u++) {
        const int c = u * 32 + lane;
        const float o = (v[u] - mean) * rstd * g[c] + b[c];
        yr[c] = o;
        if (H16) y16[(size_t)row * D + c] = __float2half_rn(o);
    }
}

// ---------------- launch ----------------------------------------------------
extern "C" void kernel_launch(void* const* d_in, const int* in_sizes, int n_in,
                              void* d_out, int out_size)
{
    const float* x      = (const float*)d_in[0];
    const float* W_qkv  = (const float*)d_in[2];
    const float* W_o    = (const float*)d_in[3];
    const float* ln1_g  = (const float*)d_in[4];
    const float* ln1_b  = (const float*)d_in[5];
    const float* W_i    = (const float*)d_in[6];
    const float* W_out2 = (const float*)d_in[7];
    const float* ln2_g  = (const float*)d_in[8];
    const float* ln2_b  = (const float*)d_in[9];
    float* out = (float*)d_out;

    __half *X16, *att16, *pre16, *inter16;
    __half *Wq16, *Wo16, *Wi16, *W216;
    float *qkv, *tmp1, *pre, *tmp2;
    cudaGetSymbolAddress((void**)&X16, g_X16);
    cudaGetSymbolAddress((void**)&qkv, g_qkv);
    cudaGetSymbolAddress((void**)&att16, g_att16);
    cudaGetSymbolAddress((void**)&tmp1, g_tmp1);
    cudaGetSymbolAddress((void**)&pre, g_pre);
    cudaGetSymbolAddress((void**)&pre16, g_pre16);
    cudaGetSymbolAddress((void**)&inter16, g_inter16);
    cudaGetSymbolAddress((void**)&tmp2, g_tmp2);
    cudaGetSymbolAddress((void**)&Wq16, g_Wqkv16);
    cudaGetSymbolAddress((void**)&Wo16, g_Wo16);
    cudaGetSymbolAddress((void**)&Wi16, g_Wi16);
    cudaGetSymbolAddress((void**)&W216, g_W216);

    cudaFuncSetAttribute(gemm_mma<0, true,  false>, cudaFuncAttributeMaxDynamicSharedMemorySize, GSMEM);
    cudaFuncSetAttribute(gemm_mma<1, true,  false>, cudaFuncAttributeMaxDynamicSharedMemorySize, GSMEM);
    cudaFuncSetAttribute(gemm_mma<2, false, true >, cudaFuncAttributeMaxDynamicSharedMemorySize, GSMEM);

    // 0) weight transpose+round; X conversion
    wT16_kernel<<<dim3(D_QKV / 32, D / 32), dim3(32, 8)>>>(W_qkv,  Wq16, D,  D_QKV);
    wT16_kernel<<<dim3(D / 32,     D / 32), dim3(32, 8)>>>(W_o,    Wo16, D,  D);
    wT16_kernel<<<dim3(DI / 32,    D / 32), dim3(32, 8)>>>(W_i,    Wi16, D,  DI);
    wT16_kernel<<<dim3(D / 32,    DI / 32), dim3(32, 8)>>>(W_out2, W216, DI, D);
    x16_kernel<<<NV * D / 256, 256>>>(x, X16, NV * D);

    // 1) qkv = X @ W_qkv                         [16384, 768]
    gemm_mma<0, true, false><<<dim3(D_QKV / 128, NV / 128), 256, GSMEM>>>(
        X16, Wq16, qkv, nullptr, nullptr, D_QKV, D);
    // 2) attention -> att (fp16)
    attn_kernel<<<NGROUPS, 256>>>(qkv, att16);
    // 3) tmp1 = att @ W_o + X
    gemm_mma<1, true, false><<<dim3(D / 128, NV / 128), 256, GSMEM>>>(
        att16, Wo16, tmp1, x, nullptr, D, D);
    // 4) pre = LN1(tmp1)  (+ fp16 copy)
    ln_kernel<true><<<NV / 8, 256>>>(tmp1, ln1_g, ln1_b, pre, pre16);
    // 5) inter = gelu(pre @ W_i)  -> fp16 only
    gemm_mma<2, false, true><<<dim3(DI / 128, NV / 128), 256, GSMEM>>>(
        pre16, Wi16, nullptr, nullptr, inter16, DI, D);
    // 6) tmp2 = inter @ W_out2 + pre
    gemm_mma<1, true, false><<<dim3(D / 128, NV / 128), 256, GSMEM>>>(
        inter16, W216, tmp2, pre, nullptr, D, DI);
    // 7) out = LN2(tmp2)
    ln_kernel<false><<<NV / 8, 256>>>(tmp2, ln2_g, ln2_b, out, nullptr);
}

// round 9
// speedup vs baseline: 1.9079x; 1.0130x over previous
#include <cuda_runtime.h>
#include <cuda_fp16.h>
#include <math.h>
#include <stdint.h>

// Problem constants (fixed by setup_inputs)
#define NV 16384
#define GRP 32
#define NGROUPS 512
#define D 256
#define NH 8
#define HD 32
#define DI 1024
#define D_QKV 768
#define LN_EPS 1e-12f

// ---------------- scratch (device globals; no allocation allowed) ----------
__device__ __half g_X16[NV * D];
__device__ __half g_qkv16[NV * D_QKV];
__device__ __half g_att16[NV * D];
__device__ float  g_pre[NV * D];
__device__ __half g_pre16[NV * D];
__device__ __half g_inter16[NV * DI];
__device__ __half g_Wqkv16[D_QKV * D];
__device__ __half g_Wo16[D * D];
__device__ __half g_Wi16[DI * D];
__device__ __half g_W216[D * DI];

// ---------------- helpers ---------------------------------------------------
__device__ __forceinline__ uint32_t smem_u32(const void* p) {
    uint32_t a;
    asm("{ .reg .u64 t; cvta.to.shared.u64 t, %1; cvt.u32.u64 %0, t; }" : "=r"(a) : "l"(p));
    return a;
}
__device__ __forceinline__ uint32_t sw128(uint32_t x) { return x ^ ((x >> 3) & 0x70); }

#define LDSM4(r0, r1, r2, r3, addr) \
    asm volatile("ldmatrix.sync.aligned.m8n8.x4.shared.b16 {%0,%1,%2,%3}, [%4];" \
                 : "=r"(r0), "=r"(r1), "=r"(r2), "=r"(r3) : "r"(addr))

#define MMA16816(d, a, b) \
    asm volatile("mma.sync.aligned.m16n8k16.row.col.f32.f16.f16.f32 " \
                 "{%0,%1,%2,%3}, {%4,%5,%6,%7}, {%8,%9}, {%0,%1,%2,%3};" \
                 : "+f"((d)[0]), "+f"((d)[1]), "+f"((d)[2]), "+f"((d)[3]) \
                 : "r"((a)[0]), "r"((a)[1]), "r"((a)[2]), "r"((a)[3]), \
                   "r"((b)[0]), "r"((b)[1]))

__device__ __forceinline__ void cpasync16(uint32_t daddr, const void* g) {
    asm volatile("cp.async.cg.shared.global [%0], [%1], 16;" :: "r"(daddr), "l"(g));
}

// load 8 halves (16B) -> 8 floats
__device__ __forceinline__ void ld8h(const __half* p, float* dst) {
    uint4 r = *(const uint4*)p;
    const __half2* h = (const __half2*)&r;
#pragma unroll
    for (int i = 0; i < 4; i++) {
        float2 f = __half22float2(h[i]);
        dst[2 * i] = f.x; dst[2 * i + 1] = f.y;
    }
}

// ---------------- conversion kernels ----------------------------------------
__global__ void __launch_bounds__(256)
x16_kernel(const float* __restrict__ x, __half* __restrict__ y, int n)
{
    int i = blockIdx.x * 256 + threadIdx.x;
    if (i < n) y[i] = __float2half_rn(x[i]);
}

// all four weights: [K,N] fp32 -> [N,K] fp16, one launch
// tiles 32x32, counts: Wqkv 24*8=192 | Wo 8*8=64 | Wi 32*8=256 | W2 8*32=256
__global__ void __launch_bounds__(256)
wall_kernel(const float* __restrict__ Wq, const float* __restrict__ Wo,
            const float* __restrict__ Wi, const float* __restrict__ W2,
            __half* __restrict__ oq, __half* __restrict__ oo,
            __half* __restrict__ oi, __half* __restrict__ o2)
{
    __shared__ float t[32][33];
    int b = blockIdx.x;
    const float* W; __half* o; int K, N;
    if (b < 192)      { W = Wq; o = oq; K = D;  N = D_QKV; }
    else if (b < 256) { W = Wo; o = oo; K = D;  N = D;     b -= 192; }
    else if (b < 512) { W = Wi; o = oi; K = D;  N = DI;    b -= 256; }
    else              { W = W2; o = o2; K = DI; N = D;     b -= 512; }
    const int nt = N / 32;
    const int n0 = (b % nt) * 32, k0 = (b / nt) * 32;
    const int tx = threadIdx.x & 31, ty = threadIdx.x >> 5;  // 32 x 8
    for (int i = ty; i < 32; i += 8)
        t[i][tx] = W[(size_t)(k0 + i) * N + n0 + tx];
    __syncthreads();
    for (int i = ty; i < 32; i += 8)
        o[(size_t)(n0 + i) * K + k0 + tx] = __float2half_rn(t[tx][i]);
}

// ---------------- fp16 mma.sync GEMM (128x128 tile, fp16 out) ---------------
#define TILE_B 16384                  // 128 rows x 128B
#define CH_B   (2 * TILE_B)
#define OFF_BW TILE_B
#define STAGES 3
#define GSMEM  (STAGES * CH_B)        // 96KB

__device__ __forceinline__ void load_chunk(const __half* __restrict__ A,
                                           const __half* __restrict__ B,
                                           int bm, int bn, int K, int k0,
                                           uint32_t sbuf, int tid)
{
#pragma unroll
    for (int t = 0; t < 4; t++) {
        const int u = tid + t * 256;
        const int row = u >> 3, c = u & 7;
        const uint32_t off = sw128(row * 128 + c * 16);
        cpasync16(sbuf + off,          A + (size_t)(bm + row) * K + k0 + c * 8);
        cpasync16(sbuf + OFF_BW + off, B + (size_t)(bn + row) * K + k0 + c * 8);
    }
}

// EPI: 0 none, 2 gelu. Output fp16 only.
template <int EPI>
__global__ void __launch_bounds__(256, 1)
gemm_mma(const __half* __restrict__ A16, const __half* __restrict__ W,
         __half* __restrict__ C16, int N, int K)
{
    extern __shared__ char smem[];
    const uint32_t sb = smem_u32(smem);
    const int tid = threadIdx.x;
    const int wid = tid >> 5, lane = tid & 31;
    const int bm = blockIdx.y * 128, bn = blockIdx.x * 128;
    const int wm = (wid & 3) * 32;
    const int wn = (wid >> 2) * 64;
    const int nch = K >> 6;

    float acc[2][8][4];
#pragma unroll
    for (int mi = 0; mi < 2; mi++)
#pragma unroll
        for (int ni = 0; ni < 8; ni++)
#pragma unroll
            for (int j = 0; j < 4; j++) acc[mi][ni][j] = 0.f;

    load_chunk(A16, W, bm, bn, K, 0, sb, tid);
    asm volatile("cp.async.commit_group;" ::: "memory");
    if (nch > 1) load_chunk(A16, W, bm, bn, K, 64, sb + CH_B, tid);
    asm volatile("cp.async.commit_group;" ::: "memory");

    for (int c = 0; c < nch; c++) {
        asm volatile("cp.async.wait_group 1;" ::: "memory");
        __syncthreads();
        if (c + 2 < nch)
            load_chunk(A16, W, bm, bn, K, (c + 2) * 64, sb + ((c + 2) % STAGES) * CH_B, tid);
        asm volatile("cp.async.commit_group;" ::: "memory");

        const uint32_t st = sb + (c % STAGES) * CH_B;
#pragma unroll
        for (int ks = 0; ks < 4; ks++) {
            const uint32_t cofs = ks * 32 + (lane >> 4) * 16;
            uint32_t a[2][4];
#pragma unroll
            for (int mi = 0; mi < 2; mi++) {
                const uint32_t ro = sw128((wm + mi * 16 + (lane & 15)) * 128 + cofs);
                LDSM4(a[mi][0], a[mi][1], a[mi][2], a[mi][3], st + ro);
            }
            uint32_t b[8][2];
#pragma unroll
            for (int np = 0; np < 4; np++) {
                const uint32_t ro = sw128((wn + np * 16 + (lane & 15)) * 128 + cofs);
                uint32_t r0, r1, r2, r3;
                LDSM4(r0, r1, r2, r3, st + OFF_BW + ro);
                b[np * 2][0] = r0; b[np * 2][1] = r2;
                b[np * 2 + 1][0] = r1; b[np * 2 + 1][1] = r3;
            }
#pragma unroll
            for (int mi = 0; mi < 2; mi++)
#pragma unroll
                for (int ni = 0; ni < 8; ni++)
                    MMA16816(acc[mi][ni], a[mi], b[ni]);
        }
        __syncthreads();
    }

#pragma unroll
    for (int mi = 0; mi < 2; mi++) {
#pragma unroll
        for (int ni = 0; ni < 8; ni++) {
            const int row0 = bm + wm + mi * 16 + (lane >> 2);
            const int col  = bn + wn + ni * 8 + (lane & 3) * 2;
#pragma unroll
            for (int h = 0; h < 2; h++) {
                const size_t gofs = (size_t)(row0 + h * 8) * N + col;
                float vx = acc[mi][ni][h * 2 + 0];
                float vy = acc[mi][ni][h * 2 + 1];
                if (EPI == 2) {
                    vx = 0.5f * vx * (1.f + erff(vx * 0.70710678118654752f));
                    vy = 0.5f * vy * (1.f + erff(vy * 0.70710678118654752f));
                }
                __half2 hh;
                hh.x = __float2half_rn(vx);
                hh.y = __float2half_rn(vy);
                *(__half2*)(C16 + gofs) = hh;
            }
        }
    }
}

// ---------------- fused GEMM + residual + LayerNorm (N=256) -----------------
// C = LN(A16@W^T + Rr); tile 128x256 (full rows), 512 threads, 16 warps.
#define LN_ATILE 16384
#define LN_WTILE 32768
#define LN_CH (LN_ATILE + LN_WTILE)      // 48KB/stage
#define LN_PITCH 264
#define LN_STAGE_B (128 * LN_PITCH * 4)  // 135168
#define LN_SMEM (LN_STAGE_B)             // > 2*LN_CH = 96KB

__device__ __forceinline__ void load_chunk_ln(const __half* __restrict__ A,
                                              const __half* __restrict__ W,
                                              int bm, int K, int k0,
                                              uint32_t sbuf, int tid)
{
#pragma unroll
    for (int t = 0; t < 2; t++) {
        const int u = tid + t * 512;           // 0..1023
        const int row = u >> 3, c = u & 7;
        cpasync16(sbuf + sw128(row * 128 + c * 16),
                  A + (size_t)(bm + row) * K + k0 + c * 8);
    }
#pragma unroll
    for (int t = 0; t < 4; t++) {
        const int u = tid + t * 512;           // 0..2047
        const int row = u >> 3, c = u & 7;
        cpasync16(sbuf + LN_ATILE + sw128(row * 128 + c * 16),
                  W + (size_t)(row) * K + k0 + c * 8);
    }
}

template <bool Y16>
__global__ void __launch_bounds__(512, 1)
gemm_ln(const __half* __restrict__ A16, const __half* __restrict__ W,
        const float* __restrict__ Rr,
        const float* __restrict__ g, const float* __restrict__ b,
        float* __restrict__ Y, __half* __restrict__ Yh, int K)
{
    extern __shared__ char smem[];
    const uint32_t sb = smem_u32(smem);
    const int tid = threadIdx.x;
    const int wid = tid >> 5, lane = tid & 31;
    const int bm = blockIdx.x * 128;
    const int wm = (wid & 3) * 32;
    const int wn = (wid >> 2) * 64;
    const int nch = K >> 6;

    float acc[2][8][4];
#pragma unroll
    for (int mi = 0; mi < 2; mi++)
#pragma unroll
        for (int ni = 0; ni < 8; ni++)
#pragma unroll
            for (int j = 0; j < 4; j++) acc[mi][ni][j] = 0.f;

    load_chunk_ln(A16, W, bm, K, 0, sb, tid);
    asm volatile("cp.async.commit_group;" ::: "memory");

    for (int c = 0; c < nch; c++) {
        if (c + 1 < nch) {
            load_chunk_ln(A16, W, bm, K, (c + 1) * 64, sb + ((c + 1) & 1) * LN_CH, tid);
            asm volatile("cp.async.commit_group;" ::: "memory");
            asm volatile("cp.async.wait_group 1;" ::: "memory");
        } else {
            asm volatile("cp.async.wait_group 0;" ::: "memory");
        }
        __syncthreads();

        const uint32_t st = sb + (c & 1) * LN_CH;
#pragma unroll
        for (int ks = 0; ks < 4; ks++) {
            const uint32_t cofs = ks * 32 + (lane >> 4) * 16;
            uint32_t a[2][4];
#pragma unroll
            for (int mi = 0; mi < 2; mi++) {
                const uint32_t ro = sw128((wm + mi * 16 + (lane & 15)) * 128 + cofs);
                LDSM4(a[mi][0], a[mi][1], a[mi][2], a[mi][3], st + ro);
            }
#pragma unroll
            for (int np = 0; np < 4; np++) {
                const uint32_t ro = sw128((wn + np * 16 + (lane & 15)) * 128 + cofs);
                uint32_t r0, r1, r2, r3;
                LDSM4(r0, r1, r2, r3, st + LN_ATILE + ro);
                uint32_t bb[2][2];
                bb[0][0] = r0; bb[0][1] = r2;
                bb[1][0] = r1; bb[1][1] = r3;
#pragma unroll
                for (int mi = 0; mi < 2; mi++)
#pragma unroll
                    for (int cc = 0; cc < 2; cc++)
                        MMA16816(acc[mi][np * 2 + cc], a[mi], bb[cc]);
            }
        }
        __syncthreads();
    }

    // stage (acc + residual) into smem, full 128x256 fp32 tile
    float* stg = (float*)smem;
#pragma unroll
    for (int mi = 0; mi < 2; mi++) {
#pragma unroll
        for (int ni = 0; ni < 8; ni++) {
            const int r0 = wm + mi * 16 + (lane >> 2);
            const int col = wn + ni * 8 + (lane & 3) * 2;
#pragma unroll
            for (int h = 0; h < 2; h++) {
                const int rr = r0 + h * 8;
                float2 res = *(const float2*)(Rr + (size_t)(bm + rr) * D + col);
                stg[rr * LN_PITCH + col]     = acc[mi][ni][h * 2 + 0] + res.x;
                stg[rr * LN_PITCH + col + 1] = acc[mi][ni][h * 2 + 1] + res.y;
            }
        }
    }
    __syncthreads();

    // LN: 4 threads per row, 64 cols each
    const int r = tid >> 2, sub = tid & 3;
    const float* rp = stg + r * LN_PITCH + sub * 64;
    float s1 = 0.f, s2 = 0.f;
#pragma unroll
    for (int j = 0; j < 16; j++) {
        float4 v = ((const float4*)rp)[j];
        s1 += v.x + v.y + v.z + v.w;
        s2 += v.x * v.x + v.y * v.y + v.z * v.z + v.w * v.w;
    }
#pragma unroll
    for (int o = 1; o < 4; o <<= 1) {
        s1 += __shfl_xor_sync(0xffffffffu, s1, o);
        s2 += __shfl_xor_sync(0xffffffffu, s2, o);
    }
    const float mean = s1 * (1.0f / D);
    const float var  = s2 * (1.0f / D) - mean * mean;
    const float rstd = rsqrtf(var + LN_EPS);

    const size_t obase = (size_t)(bm + r) * D + sub * 64;
#pragma unroll
    for (int j = 0; j < 16; j++) {
        float4 v = ((const float4*)rp)[j];
        const int c0 = sub * 64 + j * 4;
        float4 gg = *(const float4*)(g + c0);
        float4 bb = *(const float4*)(b + c0);
        float4 o;
        o.x = (v.x - mean) * rstd * gg.x + bb.x;
        o.y = (v.y - mean) * rstd * gg.y + bb.y;
        o.z = (v.z - mean) * rstd * gg.z + bb.z;
        o.w = (v.w - mean) * rstd * gg.w + bb.w;
        *(float4*)(Y + obase + j * 4) = o;
        if (Y16) {
            __half2 h0, h1;
            h0.x = __float2half_rn(o.x); h0.y = __float2half_rn(o.y);
            h1.x = __float2half_rn(o.z); h1.y = __float2half_rn(o.w);
            *(__half2*)(Yh + obase + j * 4)     = h0;
            *(__half2*)(Yh + obase + j * 4 + 2) = h1;
        }
    }
}

// ---------------- block-diagonal attention (fp16 in, fp16 out) -------------
__global__ void __launch_bounds__(256)
attn_kernel(const __half* __restrict__ qkv, __half* __restrict__ att16)
{
    __shared__ float s[NH][GRP][HD];

    const int grp  = blockIdx.x;
    const int w    = threadIdx.x >> 5;
    const int lane = threadIdx.x & 31;
    const size_t nodebase = (size_t)(grp * GRP + lane) * D_QKV + w * 96;

    // stage K (fp16 -> fp32 smem)
#pragma unroll
    for (int u = 0; u < 4; u++)
        ld8h(qkv + nodebase + 32 + u * 8, &s[w][lane][u * 8]);
    float q[32];
#pragma unroll
    for (int u = 0; u < 4; u++)
        ld8h(qkv + nodebase + u * 8, &q[u * 8]);
    __syncwarp();

    float sc[32];
    for (int j = 0; j < 32; j++) {
        const float4* kr = (const float4*)&s[w][j][0];
        float a = 0.f;
#pragma unroll
        for (int u = 0; u < 8; u++) {
            float4 kv = kr[u];
            a = fmaf(q[u * 4 + 0], kv.x, a);
            a = fmaf(q[u * 4 + 1], kv.y, a);
            a = fmaf(q[u * 4 + 2], kv.z, a);
            a = fmaf(q[u * 4 + 3], kv.w, a);
        }
        sc[j] = a * 0.17677669529663687f;
    }

    float m = -1e30f;
#pragma unroll
    for (int j = 0; j < 32; j++) m = fmaxf(m, sc[j]);
    float sum = 0.f;
#pragma unroll
    for (int j = 0; j < 32; j++) { sc[j] = expf(sc[j] - m); sum += sc[j]; }
    const float inv = 1.0f / sum;

    __syncwarp();
#pragma unroll
    for (int u = 0; u < 4; u++)
        ld8h(qkv + nodebase + 64 + u * 8, &s[w][lane][u * 8]);
    __syncwarp();

    const size_t obase = (size_t)(grp * GRP + lane) * D + w * HD;
#pragma unroll
    for (int u = 0; u < 8; u++) {
        float4 a = {0.f, 0.f, 0.f, 0.f};
        for (int j = 0; j < 32; j++) {
            float4 vv = ((const float4*)&s[w][j][0])[u];
            a.x = fmaf(sc[j], vv.x, a.x);
            a.y = fmaf(sc[j], vv.y, a.y);
            a.z = fmaf(sc[j], vv.z, a.z);
            a.w = fmaf(sc[j], vv.w, a.w);
        }
        __half2 h0, h1;
        h0.x = __float2half_rn(a.x * inv); h0.y = __float2half_rn(a.y * inv);
        h1.x = __float2half_rn(a.z * inv); h1.y = __float2half_rn(a.w * inv);
        *(__half2*)(att16 + obase + u * 4)     = h0;
        *(__half2*)(att16 + obase + u * 4 + 2) = h1;
    }
}

// ---------------- launch ----------------------------------------------------
extern "C" void kernel_launch(void* const* d_in, const int* in_sizes, int n_in,
                              void* d_out, int out_size)
{
    const float* x      = (const float*)d_in[0];
    const float* W_qkv  = (const float*)d_in[2];
    const float* W_o    = (const float*)d_in[3];
    const float* ln1_g  = (const float*)d_in[4];
    const float* ln1_b  = (const float*)d_in[5];
    const float* W_i    = (const float*)d_in[6];
    const float* W_out2 = (const float*)d_in[7];
    const float* ln2_g  = (const float*)d_in[8];
    const float* ln2_b  = (const float*)d_in[9];
    float* out = (float*)d_out;

    __half *X16, *qkv16, *att16, *pre16, *inter16;
    __half *Wq16, *Wo16, *Wi16, *W216;
    float *pre;
    cudaGetSymbolAddress((void**)&X16, g_X16);
    cudaGetSymbolAddress((void**)&qkv16, g_qkv16);
    cudaGetSymbolAddress((void**)&att16, g_att16);
    cudaGetSymbolAddress((void**)&pre, g_pre);
    cudaGetSymbolAddress((void**)&pre16, g_pre16);
    cudaGetSymbolAddress((void**)&inter16, g_inter16);
    cudaGetSymbolAddress((void**)&Wq16, g_Wqkv16);
    cudaGetSymbolAddress((void**)&Wo16, g_Wo16);
    cudaGetSymbolAddress((void**)&Wi16, g_Wi16);
    cudaGetSymbolAddress((void**)&W216, g_W216);

    cudaFuncSetAttribute(gemm_mma<0>, cudaFuncAttributeMaxDynamicSharedMemorySize, GSMEM);
    cudaFuncSetAttribute(gemm_mma<2>, cudaFuncAttributeMaxDynamicSharedMemorySize, GSMEM);
    cudaFuncSetAttribute(gemm_ln<true>,  cudaFuncAttributeMaxDynamicSharedMemorySize, LN_SMEM);
    cudaFuncSetAttribute(gemm_ln<false>, cudaFuncAttributeMaxDynamicSharedMemorySize, LN_SMEM);

    // 0) all weight transposes in one launch; X conversion
    wall_kernel<<<768, 256>>>(W_qkv, W_o, W_i, W_out2, Wq16, Wo16, Wi16, W216);
    x16_kernel<<<NV * D / 256, 256>>>(x, X16, NV * D);

    // 1) qkv16 = X @ W_qkv        [16384, 768] fp16
    gemm_mma<0><<<dim3(D_QKV / 128, NV / 128), 256, GSMEM>>>(X16, Wq16, qkv16, D_QKV, D);
    // 2) attention -> att16
    attn_kernel<<<NGROUPS, 256>>>(qkv16, att16);
    // 3+4) pre = LN1(att @ W_o + X)  (+ fp16 copy)
    gemm_ln<true><<<NV / 128, 512, LN_SMEM>>>(att16, Wo16, x, ln1_g, ln1_b, pre, pre16, D);
    // 5) inter16 = gelu(pre @ W_i)
    gemm_mma<2><<<dim3(DI / 128, NV / 128), 256, GSMEM>>>(pre16, Wi16, inter16, DI, D);
    // 6+7) out = LN2(inter @ W_out2 + pre)
    gemm_ln<false><<<NV / 128, 512, LN_SMEM>>>(inter16, W216, pre, ln2_g, ln2_b, out, nullptr, DI);
}

// round 10
// speedup vs baseline: 2.2129x; 1.1599x over previous
#include <cuda_runtime.h>
#include <cuda_fp16.h>
#include <math.h>
#include <stdint.h>

// Problem constants (fixed by setup_inputs)
#define NV 16384
#define GRP 32
#define NGROUPS 512
#define D 256
#define NH 8
#define HD 32
#define DI 1024
#define D_QKV 768
#define LN_EPS 1e-12f

// ---------------- scratch (device globals; no allocation allowed) ----------
__device__ __half g_X16[NV * D];
__device__ __half g_qkv16[NV * D_QKV];
__device__ __half g_att16[NV * D];
__device__ float  g_pre[NV * D];
__device__ __half g_pre16[NV * D];
__device__ __half g_inter16[NV * DI];
__device__ __half g_Wqkv16[D_QKV * D];
__device__ __half g_Wo16[D * D];
__device__ __half g_Wi16[DI * D];
__device__ __half g_W216[D * DI];

// ---------------- helpers ---------------------------------------------------
__device__ __forceinline__ uint32_t smem_u32(const void* p) {
    uint32_t a;
    asm("{ .reg .u64 t; cvta.to.shared.u64 t, %1; cvt.u32.u64 %0, t; }" : "=r"(a) : "l"(p));
    return a;
}
__device__ __forceinline__ uint32_t sw128(uint32_t x) { return x ^ ((x >> 3) & 0x70); }

#define LDSM4(r0, r1, r2, r3, addr) \
    asm volatile("ldmatrix.sync.aligned.m8n8.x4.shared.b16 {%0,%1,%2,%3}, [%4];" \
                 : "=r"(r0), "=r"(r1), "=r"(r2), "=r"(r3) : "r"(addr))

#define LDSM4T(r0, r1, r2, r3, addr) \
    asm volatile("ldmatrix.sync.aligned.m8n8.x4.trans.shared.b16 {%0,%1,%2,%3}, [%4];" \
                 : "=r"(r0), "=r"(r1), "=r"(r2), "=r"(r3) : "r"(addr))

#define MMA16816(d, a, b) \
    asm volatile("mma.sync.aligned.m16n8k16.row.col.f32.f16.f16.f32 " \
                 "{%0,%1,%2,%3}, {%4,%5,%6,%7}, {%8,%9}, {%0,%1,%2,%3};" \
                 : "+f"((d)[0]), "+f"((d)[1]), "+f"((d)[2]), "+f"((d)[3]) \
                 : "r"((a)[0]), "r"((a)[1]), "r"((a)[2]), "r"((a)[3]), \
                   "r"((b)[0]), "r"((b)[1]))

__device__ __forceinline__ void cpasync16(uint32_t daddr, const void* g) {
    asm volatile("cp.async.cg.shared.global [%0], [%1], 16;" :: "r"(daddr), "l"(g));
}

// ---------------- conversion kernels ----------------------------------------
__global__ void __launch_bounds__(256)
x16_kernel(const float* __restrict__ x, __half* __restrict__ y, int n)
{
    int i = blockIdx.x * 256 + threadIdx.x;
    if (i < n) y[i] = __float2half_rn(x[i]);
}

// all four weights: [K,N] fp32 -> [N,K] fp16, one launch
__global__ void __launch_bounds__(256)
wall_kernel(const float* __restrict__ Wq, const float* __restrict__ Wo,
            const float* __restrict__ Wi, const float* __restrict__ W2,
            __half* __restrict__ oq, __half* __restrict__ oo,
            __half* __restrict__ oi, __half* __restrict__ o2)
{
    __shared__ float t[32][33];
    int b = blockIdx.x;
    const float* W; __half* o; int K, N;
    if (b < 192)      { W = Wq; o = oq; K = D;  N = D_QKV; }
    else if (b < 256) { W = Wo; o = oo; K = D;  N = D;     b -= 192; }
    else if (b < 512) { W = Wi; o = oi; K = D;  N = DI;    b -= 256; }
    else              { W = W2; o = o2; K = DI; N = D;     b -= 512; }
    const int nt = N / 32;
    const int n0 = (b % nt) * 32, k0 = (b / nt) * 32;
    const int tx = threadIdx.x & 31, ty = threadIdx.x >> 5;
    for (int i = ty; i < 32; i += 8)
        t[i][tx] = W[(size_t)(k0 + i) * N + n0 + tx];
    __syncthreads();
    for (int i = ty; i < 32; i += 8)
        o[(size_t)(n0 + i) * K + k0 + tx] = __float2half_rn(t[tx][i]);
}

// ---------------- fp16 mma.sync GEMM (128x128 tile, fp16 out) ---------------
#define TILE_B 16384
#define CH_B   (2 * TILE_B)
#define OFF_BW TILE_B
#define STAGES 3
#define GSMEM  (STAGES * CH_B)

__device__ __forceinline__ void load_chunk(const __half* __restrict__ A,
                                           const __half* __restrict__ B,
                                           int bm, int bn, int K, int k0,
                                           uint32_t sbuf, int tid)
{
#pragma unroll
    for (int t = 0; t < 4; t++) {
        const int u = tid + t * 256;
        const int row = u >> 3, c = u & 7;
        const uint32_t off = sw128(row * 128 + c * 16);
        cpasync16(sbuf + off,          A + (size_t)(bm + row) * K + k0 + c * 8);
        cpasync16(sbuf + OFF_BW + off, B + (size_t)(bn + row) * K + k0 + c * 8);
    }
}

// EPI: 0 none, 2 gelu. Output fp16 only.
template <int EPI>
__global__ void __launch_bounds__(256, 1)
gemm_mma(const __half* __restrict__ A16, const __half* __restrict__ W,
         __half* __restrict__ C16, int N, int K)
{
    extern __shared__ char smem[];
    const uint32_t sb = smem_u32(smem);
    const int tid = threadIdx.x;
    const int wid = tid >> 5, lane = tid & 31;
    const int bm = blockIdx.y * 128, bn = blockIdx.x * 128;
    const int wm = (wid & 3) * 32;
    const int wn = (wid >> 2) * 64;
    const int nch = K >> 6;

    float acc[2][8][4];
#pragma unroll
    for (int mi = 0; mi < 2; mi++)
#pragma unroll
        for (int ni = 0; ni < 8; ni++)
#pragma unroll
            for (int j = 0; j < 4; j++) acc[mi][ni][j] = 0.f;

    load_chunk(A16, W, bm, bn, K, 0, sb, tid);
    asm volatile("cp.async.commit_group;" ::: "memory");
    if (nch > 1) load_chunk(A16, W, bm, bn, K, 64, sb + CH_B, tid);
    asm volatile("cp.async.commit_group;" ::: "memory");

    for (int c = 0; c < nch; c++) {
        asm volatile("cp.async.wait_group 1;" ::: "memory");
        __syncthreads();
        if (c + 2 < nch)
            load_chunk(A16, W, bm, bn, K, (c + 2) * 64, sb + ((c + 2) % STAGES) * CH_B, tid);
        asm volatile("cp.async.commit_group;" ::: "memory");

        const uint32_t st = sb + (c % STAGES) * CH_B;
#pragma unroll
        for (int ks = 0; ks < 4; ks++) {
            const uint32_t cofs = ks * 32 + (lane >> 4) * 16;
            uint32_t a[2][4];
#pragma unroll
            for (int mi = 0; mi < 2; mi++) {
                const uint32_t ro = sw128((wm + mi * 16 + (lane & 15)) * 128 + cofs);
                LDSM4(a[mi][0], a[mi][1], a[mi][2], a[mi][3], st + ro);
            }
            uint32_t b[8][2];
#pragma unroll
            for (int np = 0; np < 4; np++) {
                const uint32_t ro = sw128((wn + np * 16 + (lane & 15)) * 128 + cofs);
                uint32_t r0, r1, r2, r3;
                LDSM4(r0, r1, r2, r3, st + OFF_BW + ro);
                b[np * 2][0] = r0; b[np * 2][1] = r2;
                b[np * 2 + 1][0] = r1; b[np * 2 + 1][1] = r3;
            }
#pragma unroll
            for (int mi = 0; mi < 2; mi++)
#pragma unroll
                for (int ni = 0; ni < 8; ni++)
                    MMA16816(acc[mi][ni], a[mi], b[ni]);
        }
        __syncthreads();
    }

#pragma unroll
    for (int mi = 0; mi < 2; mi++) {
#pragma unroll
        for (int ni = 0; ni < 8; ni++) {
            const int row0 = bm + wm + mi * 16 + (lane >> 2);
            const int col  = bn + wn + ni * 8 + (lane & 3) * 2;
#pragma unroll
            for (int h = 0; h < 2; h++) {
                const size_t gofs = (size_t)(row0 + h * 8) * N + col;
                float vx = acc[mi][ni][h * 2 + 0];
                float vy = acc[mi][ni][h * 2 + 1];
                if (EPI == 2) {
                    vx = 0.5f * vx * (1.f + erff(vx * 0.70710678118654752f));
                    vy = 0.5f * vy * (1.f + erff(vy * 0.70710678118654752f));
                }
                __half2 hh;
                hh.x = __float2half_rn(vx);
                hh.y = __float2half_rn(vy);
                *(__half2*)(C16 + gofs) = hh;
            }
        }
    }
}

// ---------------- fused GEMM + residual + LayerNorm (N=256) -----------------
#define LN_ATILE 16384
#define LN_WTILE 32768
#define LN_CH (LN_ATILE + LN_WTILE)
#define LN_PITCH 264
#define LN_STAGE_B (128 * LN_PITCH * 4)
#define LN_SMEM (LN_STAGE_B)

__device__ __forceinline__ void load_chunk_ln(const __half* __restrict__ A,
                                              const __half* __restrict__ W,
                                              int bm, int K, int k0,
                                              uint32_t sbuf, int tid)
{
#pragma unroll
    for (int t = 0; t < 2; t++) {
        const int u = tid + t * 512;
        const int row = u >> 3, c = u & 7;
        cpasync16(sbuf + sw128(row * 128 + c * 16),
                  A + (size_t)(bm + row) * K + k0 + c * 8);
    }
#pragma unroll
    for (int t = 0; t < 4; t++) {
        const int u = tid + t * 512;
        const int row = u >> 3, c = u & 7;
        cpasync16(sbuf + LN_ATILE + sw128(row * 128 + c * 16),
                  W + (size_t)(row) * K + k0 + c * 8);
    }
}

template <bool Y16>
__global__ void __launch_bounds__(512, 1)
gemm_ln(const __half* __restrict__ A16, const __half* __restrict__ W,
        const float* __restrict__ Rr,
        const float* __restrict__ g, const float* __restrict__ b,
        float* __restrict__ Y, __half* __restrict__ Yh, int K)
{
    extern __shared__ char smem[];
    const uint32_t sb = smem_u32(smem);
    const int tid = threadIdx.x;
    const int wid = tid >> 5, lane = tid & 31;
    const int bm = blockIdx.x * 128;
    const int wm = (wid & 3) * 32;
    const int wn = (wid >> 2) * 64;
    const int nch = K >> 6;

    float acc[2][8][4];
#pragma unroll
    for (int mi = 0; mi < 2; mi++)
#pragma unroll
        for (int ni = 0; ni < 8; ni++)
#pragma unroll
            for (int j = 0; j < 4; j++) acc[mi][ni][j] = 0.f;

    load_chunk_ln(A16, W, bm, K, 0, sb, tid);
    asm volatile("cp.async.commit_group;" ::: "memory");

    for (int c = 0; c < nch; c++) {
        if (c + 1 < nch) {
            load_chunk_ln(A16, W, bm, K, (c + 1) * 64, sb + ((c + 1) & 1) * LN_CH, tid);
            asm volatile("cp.async.commit_group;" ::: "memory");
            asm volatile("cp.async.wait_group 1;" ::: "memory");
        } else {
            asm volatile("cp.async.wait_group 0;" ::: "memory");
        }
        __syncthreads();

        const uint32_t st = sb + (c & 1) * LN_CH;
#pragma unroll
        for (int ks = 0; ks < 4; ks++) {
            const uint32_t cofs = ks * 32 + (lane >> 4) * 16;
            uint32_t a[2][4];
#pragma unroll
            for (int mi = 0; mi < 2; mi++) {
                const uint32_t ro = sw128((wm + mi * 16 + (lane & 15)) * 128 + cofs);
                LDSM4(a[mi][0], a[mi][1], a[mi][2], a[mi][3], st + ro);
            }
#pragma unroll
            for (int np = 0; np < 4; np++) {
                const uint32_t ro = sw128((wn + np * 16 + (lane & 15)) * 128 + cofs);
                uint32_t r0, r1, r2, r3;
                LDSM4(r0, r1, r2, r3, st + LN_ATILE + ro);
                uint32_t bb[2][2];
                bb[0][0] = r0; bb[0][1] = r2;
                bb[1][0] = r1; bb[1][1] = r3;
#pragma unroll
                for (int mi = 0; mi < 2; mi++)
#pragma unroll
                    for (int cc = 0; cc < 2; cc++)
                        MMA16816(acc[mi][np * 2 + cc], a[mi], bb[cc]);
            }
        }
        __syncthreads();
    }

    float* stg = (float*)smem;
#pragma unroll
    for (int mi = 0; mi < 2; mi++) {
#pragma unroll
        for (int ni = 0; ni < 8; ni++) {
            const int r0 = wm + mi * 16 + (lane >> 2);
            const int col = wn + ni * 8 + (lane & 3) * 2;
#pragma unroll
            for (int h = 0; h < 2; h++) {
                const int rr = r0 + h * 8;
                float2 res = *(const float2*)(Rr + (size_t)(bm + rr) * D + col);
                stg[rr * LN_PITCH + col]     = acc[mi][ni][h * 2 + 0] + res.x;
                stg[rr * LN_PITCH + col + 1] = acc[mi][ni][h * 2 + 1] + res.y;
            }
        }
    }
    __syncthreads();

    const int r = tid >> 2, sub = tid & 3;
    const float* rp = stg + r * LN_PITCH + sub * 64;
    float s1 = 0.f, s2 = 0.f;
#pragma unroll
    for (int j = 0; j < 16; j++) {
        float4 v = ((const float4*)rp)[j];
        s1 += v.x + v.y + v.z + v.w;
        s2 += v.x * v.x + v.y * v.y + v.z * v.z + v.w * v.w;
    }
#pragma unroll
    for (int o = 1; o < 4; o <<= 1) {
        s1 += __shfl_xor_sync(0xffffffffu, s1, o);
        s2 += __shfl_xor_sync(0xffffffffu, s2, o);
    }
    const float mean = s1 * (1.0f / D);
    const float var  = s2 * (1.0f / D) - mean * mean;
    const float rstd = rsqrtf(var + LN_EPS);

    const size_t obase = (size_t)(bm + r) * D + sub * 64;
#pragma unroll
    for (int j = 0; j < 16; j++) {
        float4 v = ((const float4*)rp)[j];
        const int c0 = sub * 64 + j * 4;
        float4 gg = *(const float4*)(g + c0);
        float4 bb = *(const float4*)(b + c0);
        float4 o;
        o.x = (v.x - mean) * rstd * gg.x + bb.x;
        o.y = (v.y - mean) * rstd * gg.y + bb.y;
        o.z = (v.z - mean) * rstd * gg.z + bb.z;
        o.w = (v.w - mean) * rstd * gg.w + bb.w;
        *(float4*)(Y + obase + j * 4) = o;
        if (Y16) {
            __half2 h0, h1;
            h0.x = __float2half_rn(o.x); h0.y = __float2half_rn(o.y);
            h1.x = __float2half_rn(o.z); h1.y = __float2half_rn(o.w);
            *(__half2*)(Yh + obase + j * 4)     = h0;
            *(__half2*)(Yh + obase + j * 4 + 2) = h1;
        }
    }
}

// ---------------- tensor-core block-diagonal attention ----------------------
// Block = group (512 blocks), warp = head. 32x32x32 attention via mma.m16n8k16.
__global__ void __launch_bounds__(256)
attn_kernel(const __half* __restrict__ qkv, __half* __restrict__ att16)
{
    __shared__ __half Vs[NH][32][40];   // pitch 40 halves (80B): LDSM-conflict-free

    const int grp = blockIdx.x;
    const int w = threadIdx.x >> 5, lane = threadIdx.x & 31;
    const __half* base = qkv + (size_t)grp * GRP * D_QKV + w * 96;

    // stage V: lane j -> Vs[w][j][0..31]
    {
        const uint4* src = (const uint4*)(base + (size_t)lane * D_QKV + 64);
        uint4* dst = (uint4*)&Vs[w][lane][0];
        dst[0] = src[0]; dst[1] = src[1]; dst[2] = src[2]; dst[3] = src[3];
    }

    const int qr = lane >> 2, qc = (lane & 3) * 2;

    // Q fragments (A): a[mi][kk][4]
    uint32_t a[2][2][4];
#pragma unroll
    for (int mi = 0; mi < 2; mi++) {
        const __half* plo = base + (size_t)(mi * 16 + qr) * D_QKV;
        const __half* phi = base + (size_t)(mi * 16 + qr + 8) * D_QKV;
#pragma unroll
        for (int kk = 0; kk < 2; kk++) {
            a[mi][kk][0] = *(const uint32_t*)(plo + kk * 16 + qc);
            a[mi][kk][1] = *(const uint32_t*)(phi + kk * 16 + qc);
            a[mi][kk][2] = *(const uint32_t*)(plo + kk * 16 + qc + 8);
            a[mi][kk][3] = *(const uint32_t*)(phi + kk * 16 + qc + 8);
        }
    }
    // K fragments (B): bk[ni][kk][2]
    uint32_t bk[4][2][2];
#pragma unroll
    for (int ni = 0; ni < 4; ni++) {
        const __half* pn = base + (size_t)(ni * 8 + qr) * D_QKV + 32;
#pragma unroll
        for (int kk = 0; kk < 2; kk++) {
            bk[ni][kk][0] = *(const uint32_t*)(pn + kk * 16 + qc);
            bk[ni][kk][1] = *(const uint32_t*)(pn + kk * 16 + qc + 8);
        }
    }

    // S = Q @ K^T
    float s[2][4][4];
#pragma unroll
    for (int mi = 0; mi < 2; mi++)
#pragma unroll
        for (int ni = 0; ni < 4; ni++) {
#pragma unroll
            for (int j = 0; j < 4; j++) s[mi][ni][j] = 0.f;
#pragma unroll
            for (int kk = 0; kk < 2; kk++)
                MMA16816(s[mi][ni], a[mi][kk], bk[ni][kk]);
        }

    // scaled softmax per row (rows: lo = elems 0,1; hi = elems 2,3)
    const float scl = 0.17677669529663687f;
    uint32_t p[2][2][4];
    float inv_lo[2], inv_hi[2];
#pragma unroll
    for (int mi = 0; mi < 2; mi++) {
        float mlo = -1e30f, mhi = -1e30f;
#pragma unroll
        for (int ni = 0; ni < 4; ni++) {
#pragma unroll
            for (int j = 0; j < 4; j++) s[mi][ni][j] *= scl;
            mlo = fmaxf(mlo, fmaxf(s[mi][ni][0], s[mi][ni][1]));
            mhi = fmaxf(mhi, fmaxf(s[mi][ni][2], s[mi][ni][3]));
        }
#pragma unroll
        for (int o = 1; o < 4; o <<= 1) {
            mlo = fmaxf(mlo, __shfl_xor_sync(0xffffffffu, mlo, o));
            mhi = fmaxf(mhi, __shfl_xor_sync(0xffffffffu, mhi, o));
        }
        float slo = 0.f, shi = 0.f;
        float e[4][4];
#pragma unroll
        for (int ni = 0; ni < 4; ni++) {
            e[ni][0] = expf(s[mi][ni][0] - mlo);
            e[ni][1] = expf(s[mi][ni][1] - mlo);
            e[ni][2] = expf(s[mi][ni][2] - mhi);
            e[ni][3] = expf(s[mi][ni][3] - mhi);
            slo += e[ni][0] + e[ni][1];
            shi += e[ni][2] + e[ni][3];
        }
#pragma unroll
        for (int o = 1; o < 4; o <<= 1) {
            slo += __shfl_xor_sync(0xffffffffu, slo, o);
            shi += __shfl_xor_sync(0xffffffffu, shi, o);
        }
        inv_lo[mi] = 1.0f / slo;
        inv_hi[mi] = 1.0f / shi;
        // pack P into A-fragments: k-tile kk <- n-tiles 2kk, 2kk+1
#pragma unroll
        for (int kk = 0; kk < 2; kk++) {
            __half2 h;
            h.x = __float2half_rn(e[2 * kk][0]);     h.y = __float2half_rn(e[2 * kk][1]);
            p[mi][kk][0] = *(uint32_t*)&h;
            h.x = __float2half_rn(e[2 * kk][2]);     h.y = __float2half_rn(e[2 * kk][3]);
            p[mi][kk][1] = *(uint32_t*)&h;
            h.x = __float2half_rn(e[2 * kk + 1][0]); h.y = __float2half_rn(e[2 * kk + 1][1]);
            p[mi][kk][2] = *(uint32_t*)&h;
            h.x = __float2half_rn(e[2 * kk + 1][2]); h.y = __float2half_rn(e[2 * kk + 1][3]);
            p[mi][kk][3] = *(uint32_t*)&h;
        }
    }

    // V^T fragments via trans ldmatrix
    __syncwarp();
    uint32_t bv[4][2][2];
#pragma unroll
    for (int kk = 0; kk < 2; kk++) {
#pragma unroll
        for (int ch = 0; ch < 2; ch++) {
            const int vrow = kk * 16 + ((lane >> 4) * 8) + (lane & 7);
            const int vcol = ch * 16 + ((lane >> 3) & 1) * 8;
            uint32_t r0, r1, r2, r3;
            LDSM4T(r0, r1, r2, r3, smem_u32(&Vs[w][vrow][vcol]));
            bv[ch * 2][kk][0] = r0;     bv[ch * 2][kk][1] = r2;
            bv[ch * 2 + 1][kk][0] = r1; bv[ch * 2 + 1][kk][1] = r3;
        }
    }

    // O = P @ V
    float o[2][4][4];
#pragma unroll
    for (int mi = 0; mi < 2; mi++)
#pragma unroll
        for (int n2 = 0; n2 < 4; n2++) {
#pragma unroll
            for (int j = 0; j < 4; j++) o[mi][n2][j] = 0.f;
#pragma unroll
            for (int kk = 0; kk < 2; kk++)
                MMA16816(o[mi][n2], p[mi][kk], bv[n2][kk]);
        }

    // normalize + store
#pragma unroll
    for (int mi = 0; mi < 2; mi++) {
#pragma unroll
        for (int n2 = 0; n2 < 4; n2++) {
            const int col = w * HD + n2 * 8 + qc;
            const size_t rlo = (size_t)(grp * GRP + mi * 16 + qr) * D + col;
            const size_t rhi = rlo + 8 * D;
            __half2 h0, h1;
            h0.x = __float2half_rn(o[mi][n2][0] * inv_lo[mi]);
            h0.y = __float2half_rn(o[mi][n2][1] * inv_lo[mi]);
            h1.x = __float2half_rn(o[mi][n2][2] * inv_hi[mi]);
            h1.y = __float2half_rn(o[mi][n2][3] * inv_hi[mi]);
            *(__half2*)(att16 + rlo) = h0;
            *(__half2*)(att16 + rhi) = h1;
        }
    }
}

// ---------------- launch ----------------------------------------------------
extern "C" void kernel_launch(void* const* d_in, const int* in_sizes, int n_in,
                              void* d_out, int out_size)
{
    const float* x      = (const float*)d_in[0];
    const float* W_qkv  = (const float*)d_in[2];
    const float* W_o    = (const float*)d_in[3];
    const float* ln1_g  = (const float*)d_in[4];
    const float* ln1_b  = (const float*)d_in[5];
    const float* W_i    = (const float*)d_in[6];
    const float* W_out2 = (const float*)d_in[7];
    const float* ln2_g  = (const float*)d_in[8];
    const float* ln2_b  = (const float*)d_in[9];
    float* out = (float*)d_out;

    __half *X16, *qkv16, *att16, *pre16, *inter16;
    __half *Wq16, *Wo16, *Wi16, *W216;
    float *pre;
    cudaGetSymbolAddress((void**)&X16, g_X16);
    cudaGetSymbolAddress((void**)&qkv16, g_qkv16);
    cudaGetSymbolAddress((void**)&att16, g_att16);
    cudaGetSymbolAddress((void**)&pre, g_pre);
    cudaGetSymbolAddress((void**)&pre16, g_pre16);
    cudaGetSymbolAddress((void**)&inter16, g_inter16);
    cudaGetSymbolAddress((void**)&Wq16, g_Wqkv16);
    cudaGetSymbolAddress((void**)&Wo16, g_Wo16);
    cudaGetSymbolAddress((void**)&Wi16, g_Wi16);
    cudaGetSymbolAddress((void**)&W216, g_W216);

    cudaFuncSetAttribute(gemm_mma<0>, cudaFuncAttributeMaxDynamicSharedMemorySize, GSMEM);
    cudaFuncSetAttribute(gemm_mma<2>, cudaFuncAttributeMaxDynamicSharedMemorySize, GSMEM);
    cudaFuncSetAttribute(gemm_ln<true>,  cudaFuncAttributeMaxDynamicSharedMemorySize, LN_SMEM);
    cudaFuncSetAttribute(gemm_ln<false>, cudaFuncAttributeMaxDynamicSharedMemorySize, LN_SMEM);

    // 0) all weight transposes in one launch; X conversion
    wall_kernel<<<768, 256>>>(W_qkv, W_o, W_i, W_out2, Wq16, Wo16, Wi16, W216);
    x16_kernel<<<NV * D / 256, 256>>>(x, X16, NV * D);

    // 1) qkv16 = X @ W_qkv        [16384, 768] fp16
    gemm_mma<0><<<dim3(D_QKV / 128, NV / 128), 256, GSMEM>>>(X16, Wq16, qkv16, D_QKV, D);
    // 2) attention -> att16 (tensor-core)
    attn_kernel<<<NGROUPS, 256>>>(qkv16, att16);
    // 3+4) pre = LN1(att @ W_o + X)  (+ fp16 copy)
    gemm_ln<true><<<NV / 128, 512, LN_SMEM>>>(att16, Wo16, x, ln1_g, ln1_b, pre, pre16, D);
    // 5) inter16 = gelu(pre @ W_i)
    gemm_mma<2><<<dim3(DI / 128, NV / 128), 256, GSMEM>>>(pre16, Wi16, inter16, DI, D);
    // 6+7) out = LN2(inter @ W_out2 + pre)
    gemm_ln<false><<<NV / 128, 512, LN_SMEM>>>(inter16, W216, pre, ln2_g, ln2_b, out, nullptr, DI);
}

// round 11
// speedup vs baseline: 2.4163x; 1.0919x over previous
#include <cuda_runtime.h>
#include <cuda_fp16.h>
#include <math.h>
#include <stdint.h>

// Problem constants (fixed by setup_inputs)
#define NV 16384
#define GRP 32
#define NGROUPS 512
#define D 256
#define NH 8
#define HD 32
#define DI 1024
#define D_QKV 768
#define LN_EPS 1e-12f

// ---------------- scratch (device globals; no allocation allowed) ----------
__device__ __half g_X16[NV * D];
__device__ __half g_qkv16[NV * D_QKV];
__device__ __half g_att16[NV * D];
__device__ __half g_pre16[NV * D];
__device__ __half g_inter16[NV * DI];
__device__ __half g_Wqkv16[D_QKV * D];
__device__ __half g_Wo16[D * D];
__device__ __half g_Wi16[DI * D];
__device__ __half g_W216[D * DI];

// ---------------- helpers ---------------------------------------------------
__device__ __forceinline__ uint32_t smem_u32(const void* p) {
    uint32_t a;
    asm("{ .reg .u64 t; cvta.to.shared.u64 t, %1; cvt.u32.u64 %0, t; }" : "=r"(a) : "l"(p));
    return a;
}
__device__ __forceinline__ uint32_t sw128(uint32_t x) { return x ^ ((x >> 3) & 0x70); }

#define LDSM4(r0, r1, r2, r3, addr) \
    asm volatile("ldmatrix.sync.aligned.m8n8.x4.shared.b16 {%0,%1,%2,%3}, [%4];" \
                 : "=r"(r0), "=r"(r1), "=r"(r2), "=r"(r3) : "r"(addr))

#define LDSM4T(r0, r1, r2, r3, addr) \
    asm volatile("ldmatrix.sync.aligned.m8n8.x4.trans.shared.b16 {%0,%1,%2,%3}, [%4];" \
                 : "=r"(r0), "=r"(r1), "=r"(r2), "=r"(r3) : "r"(addr))

#define MMA16816(d, a, b) \
    asm volatile("mma.sync.aligned.m16n8k16.row.col.f32.f16.f16.f32 " \
                 "{%0,%1,%2,%3}, {%4,%5,%6,%7}, {%8,%9}, {%0,%1,%2,%3};" \
                 : "+f"((d)[0]), "+f"((d)[1]), "+f"((d)[2]), "+f"((d)[3]) \
                 : "r"((a)[0]), "r"((a)[1]), "r"((a)[2]), "r"((a)[3]), \
                   "r"((b)[0]), "r"((b)[1]))

__device__ __forceinline__ void cpasync16(uint32_t daddr, const void* g) {
    asm volatile("cp.async.cg.shared.global [%0], [%1], 16;" :: "r"(daddr), "l"(g));
}

// ---------------- prep: weight transposes + X conversion, one launch --------
__global__ void __launch_bounds__(256)
prep_kernel(const float* __restrict__ x,
            const float* __restrict__ Wq, const float* __restrict__ Wo,
            const float* __restrict__ Wi, const float* __restrict__ W2,
            __half* __restrict__ X16,
            __half* __restrict__ oq, __half* __restrict__ oo,
            __half* __restrict__ oi, __half* __restrict__ o2)
{
    int b = blockIdx.x;
    if (b >= 768) {
        // X conversion: 4096 blocks x 1024 elems
        const int i = (b - 768) * 1024 + threadIdx.x * 4;
        float4 v = *(const float4*)(x + i);
        __half2 h0, h1;
        h0.x = __float2half_rn(v.x); h0.y = __float2half_rn(v.y);
        h1.x = __float2half_rn(v.z); h1.y = __float2half_rn(v.w);
        *(__half2*)(X16 + i)     = h0;
        *(__half2*)(X16 + i + 2) = h1;
        return;
    }
    __shared__ float t[32][33];
    const float* W; __half* o; int K, N;
    if (b < 192)      { W = Wq; o = oq; K = D;  N = D_QKV; }
    else if (b < 256) { W = Wo; o = oo; K = D;  N = D;     b -= 192; }
    else if (b < 512) { W = Wi; o = oi; K = D;  N = DI;    b -= 256; }
    else              { W = W2; o = o2; K = DI; N = D;     b -= 512; }
    const int nt = N / 32;
    const int n0 = (b % nt) * 32, k0 = (b / nt) * 32;
    const int tx = threadIdx.x & 31, ty = threadIdx.x >> 5;
    for (int i = ty; i < 32; i += 8)
        t[i][tx] = W[(size_t)(k0 + i) * N + n0 + tx];
    __syncthreads();
    for (int i = ty; i < 32; i += 8)
        o[(size_t)(n0 + i) * K + k0 + tx] = __float2half_rn(t[tx][i]);
}

// ---------------- fp16 mma.sync GEMM (128x128 tile, fp16 out) ---------------
#define TILE_B 16384
#define CH_B   (2 * TILE_B)
#define OFF_BW TILE_B
#define STAGES 3
#define GSMEM  (STAGES * CH_B)

__device__ __forceinline__ void load_chunk(const __half* __restrict__ A,
                                           const __half* __restrict__ B,
                                           int bm, int bn, int K, int k0,
                                           uint32_t sbuf, int tid)
{
#pragma unroll
    for (int t = 0; t < 4; t++) {
        const int u = tid + t * 256;
        const int row = u >> 3, c = u & 7;
        const uint32_t off = sw128(row * 128 + c * 16);
        cpasync16(sbuf + off,          A + (size_t)(bm + row) * K + k0 + c * 8);
        cpasync16(sbuf + OFF_BW + off, B + (size_t)(bn + row) * K + k0 + c * 8);
    }
}

// EPI: 0 none, 2 gelu. Output fp16 only.
template <int EPI>
__global__ void __launch_bounds__(256)
gemm_mma(const __half* __restrict__ A16, const __half* __restrict__ W,
         __half* __restrict__ C16, int N, int K)
{
    extern __shared__ char smem[];
    const uint32_t sb = smem_u32(smem);
    const int tid = threadIdx.x;
    const int wid = tid >> 5, lane = tid & 31;
    const int bm = blockIdx.y * 128, bn = blockIdx.x * 128;
    const int wm = (wid & 3) * 32;
    const int wn = (wid >> 2) * 64;
    const int nch = K >> 6;

    float acc[2][8][4];
#pragma unroll
    for (int mi = 0; mi < 2; mi++)
#pragma unroll
        for (int ni = 0; ni < 8; ni++)
#pragma unroll
            for (int j = 0; j < 4; j++) acc[mi][ni][j] = 0.f;

    load_chunk(A16, W, bm, bn, K, 0, sb, tid);
    asm volatile("cp.async.commit_group;" ::: "memory");
    if (nch > 1) load_chunk(A16, W, bm, bn, K, 64, sb + CH_B, tid);
    asm volatile("cp.async.commit_group;" ::: "memory");

    for (int c = 0; c < nch; c++) {
        asm volatile("cp.async.wait_group 1;" ::: "memory");
        __syncthreads();
        if (c + 2 < nch)
            load_chunk(A16, W, bm, bn, K, (c + 2) * 64, sb + ((c + 2) % STAGES) * CH_B, tid);
        asm volatile("cp.async.commit_group;" ::: "memory");

        const uint32_t st = sb + (c % STAGES) * CH_B;
#pragma unroll
        for (int ks = 0; ks < 4; ks++) {
            const uint32_t cofs = ks * 32 + (lane >> 4) * 16;
            uint32_t a[2][4];
#pragma unroll
            for (int mi = 0; mi < 2; mi++) {
                const uint32_t ro = sw128((wm + mi * 16 + (lane & 15)) * 128 + cofs);
                LDSM4(a[mi][0], a[mi][1], a[mi][2], a[mi][3], st + ro);
            }
            uint32_t b[8][2];
#pragma unroll
            for (int np = 0; np < 4; np++) {
                const uint32_t ro = sw128((wn + np * 16 + (lane & 15)) * 128 + cofs);
                uint32_t r0, r1, r2, r3;
                LDSM4(r0, r1, r2, r3, st + OFF_BW + ro);
                b[np * 2][0] = r0; b[np * 2][1] = r2;
                b[np * 2 + 1][0] = r1; b[np * 2 + 1][1] = r3;
            }
#pragma unroll
            for (int mi = 0; mi < 2; mi++)
#pragma unroll
                for (int ni = 0; ni < 8; ni++)
                    MMA16816(acc[mi][ni], a[mi], b[ni]);
        }
        __syncthreads();
    }

#pragma unroll
    for (int mi = 0; mi < 2; mi++) {
#pragma unroll
        for (int ni = 0; ni < 8; ni++) {
            const int row0 = bm + wm + mi * 16 + (lane >> 2);
            const int col  = bn + wn + ni * 8 + (lane & 3) * 2;
#pragma unroll
            for (int h = 0; h < 2; h++) {
                const size_t gofs = (size_t)(row0 + h * 8) * N + col;
                float vx = acc[mi][ni][h * 2 + 0];
                float vy = acc[mi][ni][h * 2 + 1];
                if (EPI == 2) {
                    vx = 0.5f * vx * (1.f + erff(vx * 0.70710678118654752f));
                    vy = 0.5f * vy * (1.f + erff(vy * 0.70710678118654752f));
                }
                __half2 hh;
                hh.x = __float2half_rn(vx);
                hh.y = __float2half_rn(vy);
                *(__half2*)(C16 + gofs) = hh;
            }
        }
    }
}

// ---------------- fused GEMM + residual + LayerNorm, 64x256 tile ------------
// RES16: residual fp16; OUT32: write fp32 Y; OUT16: write fp16 Yh.
#define LN_ATILE 8192                   // 64 rows x 128B
#define LN_WTILE 32768                  // 256 rows x 128B
#define LN_CH (LN_ATILE + LN_WTILE)     // 40KB/stage
#define LN_PITCH 264
#define LN_SMEM (2 * LN_CH)             // 80KB (>= 64*264*4 = 67.6KB staging)

__device__ __forceinline__ void load_chunk_ln(const __half* __restrict__ A,
                                              const __half* __restrict__ W,
                                              int bm, int K, int k0,
                                              uint32_t sbuf, int tid)
{
#pragma unroll
    for (int t = 0; t < 2; t++) {
        const int u = tid + t * 256;           // 0..511 (64 rows x 8)
        const int row = u >> 3, c = u & 7;
        cpasync16(sbuf + sw128(row * 128 + c * 16),
                  A + (size_t)(bm + row) * K + k0 + c * 8);
    }
#pragma unroll
    for (int t = 0; t < 8; t++) {
        const int u = tid + t * 256;           // 0..2047 (256 rows x 8)
        const int row = u >> 3, c = u & 7;
        cpasync16(sbuf + LN_ATILE + sw128(row * 128 + c * 16),
                  W + (size_t)(row) * K + k0 + c * 8);
    }
}

template <bool RES16, bool OUT32, bool OUT16>
__global__ void __launch_bounds__(256, 2)
gemm_ln(const __half* __restrict__ A16, const __half* __restrict__ W,
        const float* __restrict__ Rf, const __half* __restrict__ Rh,
        const float* __restrict__ g, const float* __restrict__ b,
        float* __restrict__ Y, __half* __restrict__ Yh, int K)
{
    extern __shared__ char smem[];
    const uint32_t sb = smem_u32(smem);
    const int tid = threadIdx.x;
    const int wid = tid >> 5, lane = tid & 31;
    const int bm = blockIdx.x * 64;
    const int wm = (wid & 1) * 32;       // 0 or 32
    const int wn = (wid >> 1) * 64;      // 0,64,128,192
    const int nch = K >> 6;

    float acc[2][8][4];
#pragma unroll
    for (int mi = 0; mi < 2; mi++)
#pragma unroll
        for (int ni = 0; ni < 8; ni++)
#pragma unroll
            for (int j = 0; j < 4; j++) acc[mi][ni][j] = 0.f;

    load_chunk_ln(A16, W, bm, K, 0, sb, tid);
    asm volatile("cp.async.commit_group;" ::: "memory");

    for (int c = 0; c < nch; c++) {
        if (c + 1 < nch) {
            load_chunk_ln(A16, W, bm, K, (c + 1) * 64, sb + ((c + 1) & 1) * LN_CH, tid);
            asm volatile("cp.async.commit_group;" ::: "memory");
            asm volatile("cp.async.wait_group 1;" ::: "memory");
        } else {
            asm volatile("cp.async.wait_group 0;" ::: "memory");
        }
        __syncthreads();

        const uint32_t st = sb + (c & 1) * LN_CH;
#pragma unroll
        for (int ks = 0; ks < 4; ks++) {
            const uint32_t cofs = ks * 32 + (lane >> 4) * 16;
            uint32_t a[2][4];
#pragma unroll
            for (int mi = 0; mi < 2; mi++) {
                const uint32_t ro = sw128((wm + mi * 16 + (lane & 15)) * 128 + cofs);
                LDSM4(a[mi][0], a[mi][1], a[mi][2], a[mi][3], st + ro);
            }
#pragma unroll
            for (int np = 0; np < 4; np++) {
                const uint32_t ro = sw128((wn + np * 16 + (lane & 15)) * 128 + cofs);
                uint32_t r0, r1, r2, r3;
                LDSM4(r0, r1, r2, r3, st + LN_ATILE + ro);
                uint32_t bb[2][2];
                bb[0][0] = r0; bb[0][1] = r2;
                bb[1][0] = r1; bb[1][1] = r3;
#pragma unroll
                for (int mi = 0; mi < 2; mi++)
#pragma unroll
                    for (int cc = 0; cc < 2; cc++)
                        MMA16816(acc[mi][np * 2 + cc], a[mi], bb[cc]);
            }
        }
        __syncthreads();
    }

    // stage (acc + residual), 64x256 fp32 tile, pitch 264
    float* stg = (float*)smem;
#pragma unroll
    for (int mi = 0; mi < 2; mi++) {
#pragma unroll
        for (int ni = 0; ni < 8; ni++) {
            const int r0 = wm + mi * 16 + (lane >> 2);
            const int col = wn + ni * 8 + (lane & 3) * 2;
#pragma unroll
            for (int h = 0; h < 2; h++) {
                const int rr = r0 + h * 8;
                float rx, ry;
                if (RES16) {
                    __half2 rh = *(const __half2*)(Rh + (size_t)(bm + rr) * D + col);
                    float2 f = __half22float2(rh);
                    rx = f.x; ry = f.y;
                } else {
                    float2 f = *(const float2*)(Rf + (size_t)(bm + rr) * D + col);
                    rx = f.x; ry = f.y;
                }
                stg[rr * LN_PITCH + col]     = acc[mi][ni][h * 2 + 0] + rx;
                stg[rr * LN_PITCH + col + 1] = acc[mi][ni][h * 2 + 1] + ry;
            }
        }
    }
    __syncthreads();

    // LN: 4 threads per row (64 rows x 4 = 256)
    const int r = tid >> 2, sub = tid & 3;
    const float* rp = stg + r * LN_PITCH + sub * 64;
    float s1 = 0.f, s2 = 0.f;
#pragma unroll
    for (int j = 0; j < 16; j++) {
        float4 v = ((const float4*)rp)[j];
        s1 += v.x + v.y + v.z + v.w;
        s2 += v.x * v.x + v.y * v.y + v.z * v.z + v.w * v.w;
    }
#pragma unroll
    for (int o = 1; o < 4; o <<= 1) {
        s1 += __shfl_xor_sync(0xffffffffu, s1, o);
        s2 += __shfl_xor_sync(0xffffffffu, s2, o);
    }
    const float mean = s1 * (1.0f / D);
    const float var  = s2 * (1.0f / D) - mean * mean;
    const float rstd = rsqrtf(var + LN_EPS);

    const size_t obase = (size_t)(bm + r) * D + sub * 64;
#pragma unroll
    for (int j = 0; j < 16; j++) {
        float4 v = ((const float4*)rp)[j];
        const int c0 = sub * 64 + j * 4;
        float4 gg = *(const float4*)(g + c0);
        float4 bb = *(const float4*)(b + c0);
        float4 o;
        o.x = (v.x - mean) * rstd * gg.x + bb.x;
        o.y = (v.y - mean) * rstd * gg.y + bb.y;
        o.z = (v.z - mean) * rstd * gg.z + bb.z;
        o.w = (v.w - mean) * rstd * gg.w + bb.w;
        if (OUT32) *(float4*)(Y + obase + j * 4) = o;
        if (OUT16) {
            __half2 h0, h1;
            h0.x = __float2half_rn(o.x); h0.y = __float2half_rn(o.y);
            h1.x = __float2half_rn(o.z); h1.y = __float2half_rn(o.w);
            *(__half2*)(Yh + obase + j * 4)     = h0;
            *(__half2*)(Yh + obase + j * 4 + 2) = h1;
        }
    }
}

// ---------------- tensor-core block-diagonal attention ----------------------
__global__ void __launch_bounds__(256)
attn_kernel(const __half* __restrict__ qkv, __half* __restrict__ att16)
{
    __shared__ __half Vs[NH][32][40];

    const int grp = blockIdx.x;
    const int w = threadIdx.x >> 5, lane = threadIdx.x & 31;
    const __half* base = qkv + (size_t)grp * GRP * D_QKV + w * 96;

    {
        const uint4* src = (const uint4*)(base + (size_t)lane * D_QKV + 64);
        uint4* dst = (uint4*)&Vs[w][lane][0];
        dst[0] = src[0]; dst[1] = src[1]; dst[2] = src[2]; dst[3] = src[3];
    }

    const int qr = lane >> 2, qc = (lane & 3) * 2;

    uint32_t a[2][2][4];
#pragma unroll
    for (int mi = 0; mi < 2; mi++) {
        const __half* plo = base + (size_t)(mi * 16 + qr) * D_QKV;
        const __half* phi = base + (size_t)(mi * 16 + qr + 8) * D_QKV;
#pragma unroll
        for (int kk = 0; kk < 2; kk++) {
            a[mi][kk][0] = *(const uint32_t*)(plo + kk * 16 + qc);
            a[mi][kk][1] = *(const uint32_t*)(phi + kk * 16 + qc);
            a[mi][kk][2] = *(const uint32_t*)(plo + kk * 16 + qc + 8);
            a[mi][kk][3] = *(const uint32_t*)(phi + kk * 16 + qc + 8);
        }
    }
    uint32_t bk[4][2][2];
#pragma unroll
    for (int ni = 0; ni < 4; ni++) {
        const __half* pn = base + (size_t)(ni * 8 + qr) * D_QKV + 32;
#pragma unroll
        for (int kk = 0; kk < 2; kk++) {
            bk[ni][kk][0] = *(const uint32_t*)(pn + kk * 16 + qc);
            bk[ni][kk][1] = *(const uint32_t*)(pn + kk * 16 + qc + 8);
        }
    }

    float s[2][4][4];
#pragma unroll
    for (int mi = 0; mi < 2; mi++)
#pragma unroll
        for (int ni = 0; ni < 4; ni++) {
#pragma unroll
            for (int j = 0; j < 4; j++) s[mi][ni][j] = 0.f;
#pragma unroll
            for (int kk = 0; kk < 2; kk++)
                MMA16816(s[mi][ni], a[mi][kk], bk[ni][kk]);
        }

    const float scl = 0.17677669529663687f;
    uint32_t p[2][2][4];
    float inv_lo[2], inv_hi[2];
#pragma unroll
    for (int mi = 0; mi < 2; mi++) {
        float mlo = -1e30f, mhi = -1e30f;
#pragma unroll
        for (int ni = 0; ni < 4; ni++) {
#pragma unroll
            for (int j = 0; j < 4; j++) s[mi][ni][j] *= scl;
            mlo = fmaxf(mlo, fmaxf(s[mi][ni][0], s[mi][ni][1]));
            mhi = fmaxf(mhi, fmaxf(s[mi][ni][2], s[mi][ni][3]));
        }
#pragma unroll
        for (int o = 1; o < 4; o <<= 1) {
            mlo = fmaxf(mlo, __shfl_xor_sync(0xffffffffu, mlo, o));
            mhi = fmaxf(mhi, __shfl_xor_sync(0xffffffffu, mhi, o));
        }
        float slo = 0.f, shi = 0.f;
        float e[4][4];
#pragma unroll
        for (int ni = 0; ni < 4; ni++) {
            e[ni][0] = expf(s[mi][ni][0] - mlo);
            e[ni][1] = expf(s[mi][ni][1] - mlo);
            e[ni][2] = expf(s[mi][ni][2] - mhi);
            e[ni][3] = expf(s[mi][ni][3] - mhi);
            slo += e[ni][0] + e[ni][1];
            shi += e[ni][2] + e[ni][3];
        }
#pragma unroll
        for (int o = 1; o < 4; o <<= 1) {
            slo += __shfl_xor_sync(0xffffffffu, slo, o);
            shi += __shfl_xor_sync(0xffffffffu, shi, o);
        }
        inv_lo[mi] = 1.0f / slo;
        inv_hi[mi] = 1.0f / shi;
#pragma unroll
        for (int kk = 0; kk < 2; kk++) {
            __half2 h;
            h.x = __float2half_rn(e[2 * kk][0]);     h.y = __float2half_rn(e[2 * kk][1]);
            p[mi][kk][0] = *(uint32_t*)&h;
            h.x = __float2half_rn(e[2 * kk][2]);     h.y = __float2half_rn(e[2 * kk][3]);
            p[mi][kk][1] = *(uint32_t*)&h;
            h.x = __float2half_rn(e[2 * kk + 1][0]); h.y = __float2half_rn(e[2 * kk + 1][1]);
            p[mi][kk][2] = *(uint32_t*)&h;
            h.x = __float2half_rn(e[2 * kk + 1][2]); h.y = __float2half_rn(e[2 * kk + 1][3]);
            p[mi][kk][3] = *(uint32_t*)&h;
        }
    }

    __syncwarp();
    uint32_t bv[4][2][2];
#pragma unroll
    for (int kk = 0; kk < 2; kk++) {
#pragma unroll
        for (int ch = 0; ch < 2; ch++) {
            const int vrow = kk * 16 + ((lane >> 4) * 8) + (lane & 7);
            const int vcol = ch * 16 + ((lane >> 3) & 1) * 8;
            uint32_t r0, r1, r2, r3;
            LDSM4T(r0, r1, r2, r3, smem_u32(&Vs[w][vrow][vcol]));
            bv[ch * 2][kk][0] = r0;     bv[ch * 2][kk][1] = r2;
            bv[ch * 2 + 1][kk][0] = r1; bv[ch * 2 + 1][kk][1] = r3;
        }
    }

    float o[2][4][4];
#pragma unroll
    for (int mi = 0; mi < 2; mi++)
#pragma unroll
        for (int n2 = 0; n2 < 4; n2++) {
#pragma unroll
            for (int j = 0; j < 4; j++) o[mi][n2][j] = 0.f;
#pragma unroll
            for (int kk = 0; kk < 2; kk++)
                MMA16816(o[mi][n2], p[mi][kk], bv[n2][kk]);
        }

#pragma unroll
    for (int mi = 0; mi < 2; mi++) {
#pragma unroll
        for (int n2 = 0; n2 < 4; n2++) {
            const int col = w * HD + n2 * 8 + qc;
            const size_t rlo = (size_t)(grp * GRP + mi * 16 + qr) * D + col;
            const size_t rhi = rlo + 8 * D;
            __half2 h0, h1;
            h0.x = __float2half_rn(o[mi][n2][0] * inv_lo[mi]);
            h0.y = __float2half_rn(o[mi][n2][1] * inv_lo[mi]);
            h1.x = __float2half_rn(o[mi][n2][2] * inv_hi[mi]);
            h1.y = __float2half_rn(o[mi][n2][3] * inv_hi[mi]);
            *(__half2*)(att16 + rlo) = h0;
            *(__half2*)(att16 + rhi) = h1;
        }
    }
}

// ---------------- launch ----------------------------------------------------
extern "C" void kernel_launch(void* const* d_in, const int* in_sizes, int n_in,
                              void* d_out, int out_size)
{
    const float* x      = (const float*)d_in[0];
    const float* W_qkv  = (const float*)d_in[2];
    const float* W_o    = (const float*)d_in[3];
    const float* ln1_g  = (const float*)d_in[4];
    const float* ln1_b  = (const float*)d_in[5];
    const float* W_i    = (const float*)d_in[6];
    const float* W_out2 = (const float*)d_in[7];
    const float* ln2_g  = (const float*)d_in[8];
    const float* ln2_b  = (const float*)d_in[9];
    float* out = (float*)d_out;

    __half *X16, *qkv16, *att16, *pre16, *inter16;
    __half *Wq16, *Wo16, *Wi16, *W216;
    cudaGetSymbolAddress((void**)&X16, g_X16);
    cudaGetSymbolAddress((void**)&qkv16, g_qkv16);
    cudaGetSymbolAddress((void**)&att16, g_att16);
    cudaGetSymbolAddress((void**)&pre16, g_pre16);
    cudaGetSymbolAddress((void**)&inter16, g_inter16);
    cudaGetSymbolAddress((void**)&Wq16, g_Wqkv16);
    cudaGetSymbolAddress((void**)&Wo16, g_Wo16);
    cudaGetSymbolAddress((void**)&Wi16, g_Wi16);
    cudaGetSymbolAddress((void**)&W216, g_W216);

    cudaFuncSetAttribute(gemm_mma<0>, cudaFuncAttributeMaxDynamicSharedMemorySize, GSMEM);
    cudaFuncSetAttribute(gemm_mma<2>, cudaFuncAttributeMaxDynamicSharedMemorySize, GSMEM);
    cudaFuncSetAttribute((const void*)gemm_ln<false, false, true>,
                         cudaFuncAttributeMaxDynamicSharedMemorySize, LN_SMEM);
    cudaFuncSetAttribute((const void*)gemm_ln<true, true, false>,
                         cudaFuncAttributeMaxDynamicSharedMemorySize, LN_SMEM);

    // 0) prep: weight transposes + X conversion (one launch)
    prep_kernel<<<768 + NV * D / 1024, 256>>>(x, W_qkv, W_o, W_i, W_out2,
                                              X16, Wq16, Wo16, Wi16, W216);

    // 1) qkv16 = X @ W_qkv        [16384, 768] fp16
    gemm_mma<0><<<dim3(D_QKV / 128, NV / 128), 256, GSMEM>>>(X16, Wq16, qkv16, D_QKV, D);
    // 2) attention -> att16 (tensor-core)
    attn_kernel<<<NGROUPS, 256>>>(qkv16, att16);
    // 3+4) pre16 = LN1(att @ W_o + X)
    gemm_ln<false, false, true><<<NV / 64, 256, LN_SMEM>>>(
        att16, Wo16, x, nullptr, ln1_g, ln1_b, nullptr, pre16, D);
    // 5) inter16 = gelu(pre @ W_i)
    gemm_mma<2><<<dim3(DI / 128, NV / 128), 256, GSMEM>>>(pre16, Wi16, inter16, DI, D);
    // 6+7) out = LN2(inter @ W_out2 + pre16)
    gemm_ln<true, true, false><<<NV / 64, 256, LN_SMEM>>>(
        inter16, W216, nullptr, pre16, ln2_g, ln2_b, out, nullptr, DI);
}

// round 12
// speedup vs baseline: 2.6864x; 1.1118x over previous
#include <cuda_runtime.h>
#include <cuda_fp16.h>
#include <math.h>
#include <stdint.h>

// Problem constants (fixed by setup_inputs)
#define NV 16384
#define GRP 32
#define NGROUPS 512
#define D 256
#define NH 8
#define HD 32
#define DI 1024
#define D_QKV 768
#define LN_EPS 1e-12f

// ---------------- scratch (device globals; no allocation allowed) ----------
__device__ __half g_X16[NV * D];
__device__ __half g_qkv16[NV * D_QKV];
__device__ __half g_att16[NV * D];
__device__ __half g_pre16[NV * D];
__device__ __half g_inter16[NV * DI];
__device__ __half g_Wqkv16[D_QKV * D];
__device__ __half g_Wo16[D * D];
__device__ __half g_Wi16[DI * D];
__device__ __half g_W216[D * DI];

// ---------------- helpers ---------------------------------------------------
__device__ __forceinline__ uint32_t smem_u32(const void* p) {
    uint32_t a;
    asm("{ .reg .u64 t; cvta.to.shared.u64 t, %1; cvt.u32.u64 %0, t; }" : "=r"(a) : "l"(p));
    return a;
}
__device__ __forceinline__ uint32_t sw128(uint32_t x) { return x ^ ((x >> 3) & 0x70); }

#define LDSM4(r0, r1, r2, r3, addr) \
    asm volatile("ldmatrix.sync.aligned.m8n8.x4.shared.b16 {%0,%1,%2,%3}, [%4];" \
                 : "=r"(r0), "=r"(r1), "=r"(r2), "=r"(r3) : "r"(addr))

#define LDSM4T(r0, r1, r2, r3, addr) \
    asm volatile("ldmatrix.sync.aligned.m8n8.x4.trans.shared.b16 {%0,%1,%2,%3}, [%4];" \
                 : "=r"(r0), "=r"(r1), "=r"(r2), "=r"(r3) : "r"(addr))

#define MMA16816(d, a, b) \
    asm volatile("mma.sync.aligned.m16n8k16.row.col.f32.f16.f16.f32 " \
                 "{%0,%1,%2,%3}, {%4,%5,%6,%7}, {%8,%9}, {%0,%1,%2,%3};" \
                 : "+f"((d)[0]), "+f"((d)[1]), "+f"((d)[2]), "+f"((d)[3]) \
                 : "r"((a)[0]), "r"((a)[1]), "r"((a)[2]), "r"((a)[3]), \
                   "r"((b)[0]), "r"((b)[1]))

__device__ __forceinline__ void cpasync16(uint32_t daddr, const void* g) {
    asm volatile("cp.async.cg.shared.global [%0], [%1], 16;" :: "r"(daddr), "l"(g));
}

// ---------------- prep: weight transposes + X conversion, one launch --------
__global__ void __launch_bounds__(256)
prep_kernel(const float* __restrict__ x,
            const float* __restrict__ Wq, const float* __restrict__ Wo,
            const float* __restrict__ Wi, const float* __restrict__ W2,
            __half* __restrict__ X16,
            __half* __restrict__ oq, __half* __restrict__ oo,
            __half* __restrict__ oi, __half* __restrict__ o2)
{
    int b = blockIdx.x;
    if (b >= 768) {
        const int i = (b - 768) * 1024 + threadIdx.x * 4;
        float4 v = *(const float4*)(x + i);
        __half2 h0, h1;
        h0.x = __float2half_rn(v.x); h0.y = __float2half_rn(v.y);
        h1.x = __float2half_rn(v.z); h1.y = __float2half_rn(v.w);
        *(__half2*)(X16 + i)     = h0;
        *(__half2*)(X16 + i + 2) = h1;
        return;
    }
    __shared__ float t[32][33];
    const float* W; __half* o; int K, N;
    if (b < 192)      { W = Wq; o = oq; K = D;  N = D_QKV; }
    else if (b < 256) { W = Wo; o = oo; K = D;  N = D;     b -= 192; }
    else if (b < 512) { W = Wi; o = oi; K = D;  N = DI;    b -= 256; }
    else              { W = W2; o = o2; K = DI; N = D;     b -= 512; }
    const int nt = N / 32;
    const int n0 = (b % nt) * 32, k0 = (b / nt) * 32;
    const int tx = threadIdx.x & 31, ty = threadIdx.x >> 5;
    for (int i = ty; i < 32; i += 8)
        t[i][tx] = W[(size_t)(k0 + i) * N + n0 + tx];
    __syncthreads();
    for (int i = ty; i < 32; i += 8)
        o[(size_t)(n0 + i) * K + k0 + tx] = __float2half_rn(t[tx][i]);
}

// ---------------- fp16 mma.sync GEMM (128x128 tile, fp16 out) ---------------
#define TILE_B 16384
#define CH_B   (2 * TILE_B)
#define OFF_BW TILE_B
#define STAGES 3
#define GSMEM  (STAGES * CH_B)

__device__ __forceinline__ void load_chunk(const __half* __restrict__ A,
                                           const __half* __restrict__ B,
                                           int bm, int bn, int K, int k0,
                                           uint32_t sbuf, int tid)
{
#pragma unroll
    for (int t = 0; t < 4; t++) {
        const int u = tid + t * 256;
        const int row = u >> 3, c = u & 7;
        const uint32_t off = sw128(row * 128 + c * 16);
        cpasync16(sbuf + off,          A + (size_t)(bm + row) * K + k0 + c * 8);
        cpasync16(sbuf + OFF_BW + off, B + (size_t)(bn + row) * K + k0 + c * 8);
    }
}

// EPI: 0 none, 2 gelu. Output fp16 only.
template <int EPI>
__global__ void __launch_bounds__(256)
gemm_mma(const __half* __restrict__ A16, const __half* __restrict__ W,
         __half* __restrict__ C16, int N, int K)
{
    extern __shared__ char smem[];
    const uint32_t sb = smem_u32(smem);
    const int tid = threadIdx.x;
    const int wid = tid >> 5, lane = tid & 31;
    const int bm = blockIdx.y * 128, bn = blockIdx.x * 128;
    const int wm = (wid & 3) * 32;
    const int wn = (wid >> 2) * 64;
    const int nch = K >> 6;

    float acc[2][8][4];
#pragma unroll
    for (int mi = 0; mi < 2; mi++)
#pragma unroll
        for (int ni = 0; ni < 8; ni++)
#pragma unroll
            for (int j = 0; j < 4; j++) acc[mi][ni][j] = 0.f;

    load_chunk(A16, W, bm, bn, K, 0, sb, tid);
    asm volatile("cp.async.commit_group;" ::: "memory");
    if (nch > 1) load_chunk(A16, W, bm, bn, K, 64, sb + CH_B, tid);
    asm volatile("cp.async.commit_group;" ::: "memory");

    for (int c = 0; c < nch; c++) {
        asm volatile("cp.async.wait_group 1;" ::: "memory");
        __syncthreads();
        if (c + 2 < nch)
            load_chunk(A16, W, bm, bn, K, (c + 2) * 64, sb + ((c + 2) % STAGES) * CH_B, tid);
        asm volatile("cp.async.commit_group;" ::: "memory");

        const uint32_t st = sb + (c % STAGES) * CH_B;
#pragma unroll
        for (int ks = 0; ks < 4; ks++) {
            const uint32_t cofs = ks * 32 + (lane >> 4) * 16;
            uint32_t a[2][4];
#pragma unroll
            for (int mi = 0; mi < 2; mi++) {
                const uint32_t ro = sw128((wm + mi * 16 + (lane & 15)) * 128 + cofs);
                LDSM4(a[mi][0], a[mi][1], a[mi][2], a[mi][3], st + ro);
            }
            uint32_t b[8][2];
#pragma unroll
            for (int np = 0; np < 4; np++) {
                const uint32_t ro = sw128((wn + np * 16 + (lane & 15)) * 128 + cofs);
                uint32_t r0, r1, r2, r3;
                LDSM4(r0, r1, r2, r3, st + OFF_BW + ro);
                b[np * 2][0] = r0; b[np * 2][1] = r2;
                b[np * 2 + 1][0] = r1; b[np * 2 + 1][1] = r3;
            }
#pragma unroll
            for (int mi = 0; mi < 2; mi++)
#pragma unroll
                for (int ni = 0; ni < 8; ni++)
                    MMA16816(acc[mi][ni], a[mi], b[ni]);
        }
        __syncthreads();
    }

#pragma unroll
    for (int mi = 0; mi < 2; mi++) {
#pragma unroll
        for (int ni = 0; ni < 8; ni++) {
            const int row0 = bm + wm + mi * 16 + (lane >> 2);
            const int col  = bn + wn + ni * 8 + (lane & 3) * 2;
#pragma unroll
            for (int h = 0; h < 2; h++) {
                const size_t gofs = (size_t)(row0 + h * 8) * N + col;
                float vx = acc[mi][ni][h * 2 + 0];
                float vy = acc[mi][ni][h * 2 + 1];
                if (EPI == 2) {
                    vx = 0.5f * vx * (1.f + erff(vx * 0.70710678118654752f));
                    vy = 0.5f * vy * (1.f + erff(vy * 0.70710678118654752f));
                }
                __half2 hh;
                hh.x = __float2half_rn(vx);
                hh.y = __float2half_rn(vy);
                *(__half2*)(C16 + gofs) = hh;
            }
        }
    }
}

// ---------------- fused GEMM + residual + LayerNorm, MT x 256 tile ----------
// Register-resident LN epilogue (no smem staging).
// MT=32: 8 n-warps of 32 cols, 3 CTAs/SM.  MT=64: 2x4 warps, 2 CTAs/SM.
template <int MT> struct LnCfg {
    static const int WARPS_M = MT / 32;
    static const int WARPS_N = 8 / WARPS_M;
    static const int NTILE   = 256 / WARPS_N;   // cols per warp
    static const int NI      = NTILE / 8;       // n-tiles of 8
    static const int ATILE_B = MT * 128;
    static const int CH      = ATILE_B + 32768; // + W tile (256 rows x 128B)
    static const int SMEM    = 2 * CH + MT * WARPS_N * 2 * 4;
};

template <int MT>
__device__ __forceinline__ void load_chunk_ln(const __half* __restrict__ A,
                                              const __half* __restrict__ W,
                                              int bm, int K, int k0,
                                              uint32_t sbuf, int tid)
{
#pragma unroll
    for (int t = 0; t < MT / 32; t++) {
        const int u = tid + t * 256;           // MT rows x 8
        const int row = u >> 3, c = u & 7;
        cpasync16(sbuf + sw128(row * 128 + c * 16),
                  A + (size_t)(bm + row) * K + k0 + c * 8);
    }
#pragma unroll
    for (int t = 0; t < 8; t++) {
        const int u = tid + t * 256;           // 256 rows x 8
        const int row = u >> 3, c = u & 7;
        cpasync16(sbuf + LnCfg<MT>::ATILE_B + sw128(row * 128 + c * 16),
                  W + (size_t)(row) * K + k0 + c * 8);
    }
}

template <int MT, bool RES16, bool OUT32, bool OUT16>
__global__ void __launch_bounds__(256, MT == 32 ? 3 : 2)
gemm_ln(const __half* __restrict__ A16, const __half* __restrict__ W,
        const float* __restrict__ Rf, const __half* __restrict__ Rh,
        const float* __restrict__ g, const float* __restrict__ b,
        float* __restrict__ Y, __half* __restrict__ Yh, int K)
{
    typedef LnCfg<MT> C;
    extern __shared__ char smem[];
    const uint32_t sb = smem_u32(smem);
    const int tid = threadIdx.x;
    const int wid = tid >> 5, lane = tid & 31;
    const int bm = blockIdx.x * MT;
    const int WM = (wid % C::WARPS_M) * 32;
    const int WN = (wid / C::WARPS_M) * C::NTILE;
    const int wq = wid / C::WARPS_M;
    const int nch = K >> 6;

    float acc[2][C::NI][4];
#pragma unroll
    for (int mi = 0; mi < 2; mi++)
#pragma unroll
        for (int ni = 0; ni < C::NI; ni++)
#pragma unroll
            for (int j = 0; j < 4; j++) acc[mi][ni][j] = 0.f;

    load_chunk_ln<MT>(A16, W, bm, K, 0, sb, tid);
    asm volatile("cp.async.commit_group;" ::: "memory");

    for (int c = 0; c < nch; c++) {
        if (c + 1 < nch) {
            load_chunk_ln<MT>(A16, W, bm, K, (c + 1) * 64, sb + ((c + 1) & 1) * C::CH, tid);
            asm volatile("cp.async.commit_group;" ::: "memory");
            asm volatile("cp.async.wait_group 1;" ::: "memory");
        } else {
            asm volatile("cp.async.wait_group 0;" ::: "memory");
        }
        __syncthreads();

        const uint32_t st = sb + (c & 1) * C::CH;
#pragma unroll
        for (int ks = 0; ks < 4; ks++) {
            const uint32_t cofs = ks * 32 + (lane >> 4) * 16;
            uint32_t a[2][4];
#pragma unroll
            for (int mi = 0; mi < 2; mi++) {
                const uint32_t ro = sw128((WM + mi * 16 + (lane & 15)) * 128 + cofs);
                LDSM4(a[mi][0], a[mi][1], a[mi][2], a[mi][3], st + ro);
            }
#pragma unroll
            for (int np = 0; np < C::NI / 2; np++) {
                const uint32_t ro = sw128((WN + np * 16 + (lane & 15)) * 128 + cofs);
                uint32_t r0, r1, r2, r3;
                LDSM4(r0, r1, r2, r3, st + C::ATILE_B + ro);
                uint32_t bb[2][2];
                bb[0][0] = r0; bb[0][1] = r2;
                bb[1][0] = r1; bb[1][1] = r3;
#pragma unroll
                for (int mi = 0; mi < 2; mi++)
#pragma unroll
                    for (int cc = 0; cc < 2; cc++)
                        MMA16816(acc[mi][np * 2 + cc], a[mi], bb[cc]);
            }
        }
        __syncthreads();
    }

    // add residual into accumulators
#pragma unroll
    for (int mi = 0; mi < 2; mi++)
#pragma unroll
        for (int h = 0; h < 2; h++) {
            const int row = WM + mi * 16 + h * 8 + (lane >> 2);
#pragma unroll
            for (int ni = 0; ni < C::NI; ni++) {
                const int col = WN + ni * 8 + (lane & 3) * 2;
                float rx, ry;
                if (RES16) {
                    float2 f = __half22float2(*(const __half2*)(Rh + (size_t)(bm + row) * D + col));
                    rx = f.x; ry = f.y;
                } else {
                    float2 f = *(const float2*)(Rf + (size_t)(bm + row) * D + col);
                    rx = f.x; ry = f.y;
                }
                acc[mi][ni][h * 2 + 0] += rx;
                acc[mi][ni][h * 2 + 1] += ry;
            }
        }

    // per-row partial sums -> cross-warp reduce via small smem buffer
    float* sp = (float*)(smem + 2 * C::CH);   // [MT][WARPS_N][2]
#pragma unroll
    for (int mi = 0; mi < 2; mi++)
#pragma unroll
        for (int h = 0; h < 2; h++) {
            float s1 = 0.f, s2 = 0.f;
#pragma unroll
            for (int ni = 0; ni < C::NI; ni++) {
                float vx = acc[mi][ni][h * 2], vy = acc[mi][ni][h * 2 + 1];
                s1 += vx + vy;
                s2 += vx * vx + vy * vy;
            }
#pragma unroll
            for (int o = 1; o < 4; o <<= 1) {
                s1 += __shfl_xor_sync(0xffffffffu, s1, o);
                s2 += __shfl_xor_sync(0xffffffffu, s2, o);
            }
            if ((lane & 3) == 0) {
                const int row = WM + mi * 16 + h * 8 + (lane >> 2);
                sp[(row * C::WARPS_N + wq) * 2 + 0] = s1;
                sp[(row * C::WARPS_N + wq) * 2 + 1] = s2;
            }
        }
    __syncthreads();

    // normalize + store
#pragma unroll
    for (int mi = 0; mi < 2; mi++)
#pragma unroll
        for (int h = 0; h < 2; h++) {
            const int row = WM + mi * 16 + h * 8 + (lane >> 2);
            float s1 = 0.f, s2 = 0.f;
#pragma unroll
            for (int q = 0; q < C::WARPS_N; q++) {
                s1 += sp[(row * C::WARPS_N + q) * 2 + 0];
                s2 += sp[(row * C::WARPS_N + q) * 2 + 1];
            }
            const float mean = s1 * (1.0f / D);
            const float var  = s2 * (1.0f / D) - mean * mean;
            const float rstd = rsqrtf(var + LN_EPS);
#pragma unroll
            for (int ni = 0; ni < C::NI; ni++) {
                const int col = WN + ni * 8 + (lane & 3) * 2;
                const float2 gg = *(const float2*)(g + col);
                const float2 bb = *(const float2*)(b + col);
                const float ox = (acc[mi][ni][h * 2]     - mean) * rstd * gg.x + bb.x;
                const float oy = (acc[mi][ni][h * 2 + 1] - mean) * rstd * gg.y + bb.y;
                const size_t gofs = (size_t)(bm + row) * D + col;
                if (OUT32) {
                    float2 f; f.x = ox; f.y = oy;
                    *(float2*)(Y + gofs) = f;
                }
                if (OUT16) {
                    __half2 hh;
                    hh.x = __float2half_rn(ox);
                    hh.y = __float2half_rn(oy);
                    *(__half2*)(Yh + gofs) = hh;
                }
            }
        }
}

// ---------------- tensor-core block-diagonal attention ----------------------
__global__ void __launch_bounds__(256)
attn_kernel(const __half* __restrict__ qkv, __half* __restrict__ att16)
{
    __shared__ __half Vs[NH][32][40];

    const int grp = blockIdx.x;
    const int w = threadIdx.x >> 5, lane = threadIdx.x & 31;
    const __half* base = qkv + (size_t)grp * GRP * D_QKV + w * 96;

    {
        const uint4* src = (const uint4*)(base + (size_t)lane * D_QKV + 64);
        uint4* dst = (uint4*)&Vs[w][lane][0];
        dst[0] = src[0]; dst[1] = src[1]; dst[2] = src[2]; dst[3] = src[3];
    }

    const int qr = lane >> 2, qc = (lane & 3) * 2;

    uint32_t a[2][2][4];
#pragma unroll
    for (int mi = 0; mi < 2; mi++) {
        const __half* plo = base + (size_t)(mi * 16 + qr) * D_QKV;
        const __half* phi = base + (size_t)(mi * 16 + qr + 8) * D_QKV;
#pragma unroll
        for (int kk = 0; kk < 2; kk++) {
            a[mi][kk][0] = *(const uint32_t*)(plo + kk * 16 + qc);
            a[mi][kk][1] = *(const uint32_t*)(phi + kk * 16 + qc);
            a[mi][kk][2] = *(const uint32_t*)(plo + kk * 16 + qc + 8);
            a[mi][kk][3] = *(const uint32_t*)(phi + kk * 16 + qc + 8);
        }
    }
    uint32_t bk[4][2][2];
#pragma unroll
    for (int ni = 0; ni < 4; ni++) {
        const __half* pn = base + (size_t)(ni * 8 + qr) * D_QKV + 32;
#pragma unroll
        for (int kk = 0; kk < 2; kk++) {
            bk[ni][kk][0] = *(const uint32_t*)(pn + kk * 16 + qc);
            bk[ni][kk][1] = *(const uint32_t*)(pn + kk * 16 + qc + 8);
        }
    }

    float s[2][4][4];
#pragma unroll
    for (int mi = 0; mi < 2; mi++)
#pragma unroll
        for (int ni = 0; ni < 4; ni++) {
#pragma unroll
            for (int j = 0; j < 4; j++) s[mi][ni][j] = 0.f;
#pragma unroll
            for (int kk = 0; kk < 2; kk++)
                MMA16816(s[mi][ni], a[mi][kk], bk[ni][kk]);
        }

    const float scl = 0.17677669529663687f;
    uint32_t p[2][2][4];
    float inv_lo[2], inv_hi[2];
#pragma unroll
    for (int mi = 0; mi < 2; mi++) {
        float mlo = -1e30f, mhi = -1e30f;
#pragma unroll
        for (int ni = 0; ni < 4; ni++) {
#pragma unroll
            for (int j = 0; j < 4; j++) s[mi][ni][j] *= scl;
            mlo = fmaxf(mlo, fmaxf(s[mi][ni][0], s[mi][ni][1]));
            mhi = fmaxf(mhi, fmaxf(s[mi][ni][2], s[mi][ni][3]));
        }
#pragma unroll
        for (int o = 1; o < 4; o <<= 1) {
            mlo = fmaxf(mlo, __shfl_xor_sync(0xffffffffu, mlo, o));
            mhi = fmaxf(mhi, __shfl_xor_sync(0xffffffffu, mhi, o));
        }
        float slo = 0.f, shi = 0.f;
        float e[4][4];
#pragma unroll
        for (int ni = 0; ni < 4; ni++) {
            e[ni][0] = expf(s[mi][ni][0] - mlo);
            e[ni][1] = expf(s[mi][ni][1] - mlo);
            e[ni][2] = expf(s[mi][ni][2] - mhi);
            e[ni][3] = expf(s[mi][ni][3] - mhi);
            slo += e[ni][0] + e[ni][1];
            shi += e[ni][2] + e[ni][3];
        }
#pragma unroll
        for (int o = 1; o < 4; o <<= 1) {
            slo += __shfl_xor_sync(0xffffffffu, slo, o);
            shi += __shfl_xor_sync(0xffffffffu, shi, o);
        }
        inv_lo[mi] = 1.0f / slo;
        inv_hi[mi] = 1.0f / shi;
#pragma unroll
        for (int kk = 0; kk < 2; kk++) {
            __half2 h;
            h.x = __float2half_rn(e[2 * kk][0]);     h.y = __float2half_rn(e[2 * kk][1]);
            p[mi][kk][0] = *(uint32_t*)&h;
            h.x = __float2half_rn(e[2 * kk][2]);     h.y = __float2half_rn(e[2 * kk][3]);
            p[mi][kk][1] = *(uint32_t*)&h;
            h.x = __float2half_rn(e[2 * kk + 1][0]); h.y = __float2half_rn(e[2 * kk + 1][1]);
            p[mi][kk][2] = *(uint32_t*)&h;
            h.x = __float2half_rn(e[2 * kk + 1][2]); h.y = __float2half_rn(e[2 * kk + 1][3]);
            p[mi][kk][3] = *(uint32_t*)&h;
        }
    }

    __syncwarp();
    uint32_t bv[4][2][2];
#pragma unroll
    for (int kk = 0; kk < 2; kk++) {
#pragma unroll
        for (int ch = 0; ch < 2; ch++) {
            const int vrow = kk * 16 + ((lane >> 4) * 8) + (lane & 7);
            const int vcol = ch * 16 + ((lane >> 3) & 1) * 8;
            uint32_t r0, r1, r2, r3;
            LDSM4T(r0, r1, r2, r3, smem_u32(&Vs[w][vrow][vcol]));
            bv[ch * 2][kk][0] = r0;     bv[ch * 2][kk][1] = r2;
            bv[ch * 2 + 1][kk][0] = r1; bv[ch * 2 + 1][kk][1] = r3;
        }
    }

    float o[2][4][4];
#pragma unroll
    for (int mi = 0; mi < 2; mi++)
#pragma unroll
        for (int n2 = 0; n2 < 4; n2++) {
#pragma unroll
            for (int j = 0; j < 4; j++) o[mi][n2][j] = 0.f;
#pragma unroll
            for (int kk = 0; kk < 2; kk++)
                MMA16816(o[mi][n2], p[mi][kk], bv[n2][kk]);
        }

#pragma unroll
    for (int mi = 0; mi < 2; mi++) {
#pragma unroll
        for (int n2 = 0; n2 < 4; n2++) {
            const int col = w * HD + n2 * 8 + qc;
            const size_t rlo = (size_t)(grp * GRP + mi * 16 + qr) * D + col;
            const size_t rhi = rlo + 8 * D;
            __half2 h0, h1;
            h0.x = __float2half_rn(o[mi][n2][0] * inv_lo[mi]);
            h0.y = __float2half_rn(o[mi][n2][1] * inv_lo[mi]);
            h1.x = __float2half_rn(o[mi][n2][2] * inv_hi[mi]);
            h1.y = __float2half_rn(o[mi][n2][3] * inv_hi[mi]);
            *(__half2*)(att16 + rlo) = h0;
            *(__half2*)(att16 + rhi) = h1;
        }
    }
}

// ---------------- launch ----------------------------------------------------
extern "C" void kernel_launch(void* const* d_in, const int* in_sizes, int n_in,
                              void* d_out, int out_size)
{
    const float* x      = (const float*)d_in[0];
    const float* W_qkv  = (const float*)d_in[2];
    const float* W_o    = (const float*)d_in[3];
    const float* ln1_g  = (const float*)d_in[4];
    const float* ln1_b  = (const float*)d_in[5];
    const float* W_i    = (const float*)d_in[6];
    const float* W_out2 = (const float*)d_in[7];
    const float* ln2_g  = (const float*)d_in[8];
    const float* ln2_b  = (const float*)d_in[9];
    float* out = (float*)d_out;

    __half *X16, *qkv16, *att16, *pre16, *inter16;
    __half *Wq16, *Wo16, *Wi16, *W216;
    cudaGetSymbolAddress((void**)&X16, g_X16);
    cudaGetSymbolAddress((void**)&qkv16, g_qkv16);
    cudaGetSymbolAddress((void**)&att16, g_att16);
    cudaGetSymbolAddress((void**)&pre16, g_pre16);
    cudaGetSymbolAddress((void**)&inter16, g_inter16);
    cudaGetSymbolAddress((void**)&Wq16, g_Wqkv16);
    cudaGetSymbolAddress((void**)&Wo16, g_Wo16);
    cudaGetSymbolAddress((void**)&Wi16, g_Wi16);
    cudaGetSymbolAddress((void**)&W216, g_W216);

    cudaFuncSetAttribute(gemm_mma<0>, cudaFuncAttributeMaxDynamicSharedMemorySize, GSMEM);
    cudaFuncSetAttribute(gemm_mma<2>, cudaFuncAttributeMaxDynamicSharedMemorySize, GSMEM);
    cudaFuncSetAttribute((const void*)gemm_ln<32, false, false, true>,
                         cudaFuncAttributeMaxDynamicSharedMemorySize, LnCfg<32>::SMEM);
    cudaFuncSetAttribute((const void*)gemm_ln<64, true, true, false>,
                         cudaFuncAttributeMaxDynamicSharedMemorySize, LnCfg<64>::SMEM);

    // 0) prep: weight transposes + X conversion (one launch)
    prep_kernel<<<768 + NV * D / 1024, 256>>>(x, W_qkv, W_o, W_i, W_out2,
                                              X16, Wq16, Wo16, Wi16, W216);

    // 1) qkv16 = X @ W_qkv        [16384, 768] fp16
    gemm_mma<0><<<dim3(D_QKV / 128, NV / 128), 256, GSMEM>>>(X16, Wq16, qkv16, D_QKV, D);
    // 2) attention -> att16 (tensor-core)
    attn_kernel<<<NGROUPS, 256>>>(qkv16, att16);
    // 3+4) pre16 = LN1(att @ W_o + X)   [32-row tiles, 3 CTAs/SM]
    gemm_ln<32, false, false, true><<<NV / 32, 256, LnCfg<32>::SMEM>>>(
        att16, Wo16, x, nullptr, ln1_g, ln1_b, nullptr, pre16, D);
    // 5) inter16 = gelu(pre @ W_i)
    gemm_mma<2><<<dim3(DI / 128, NV / 128), 256, GSMEM>>>(pre16, Wi16, inter16, DI, D);
    // 6+7) out = LN2(inter @ W_out2 + pre16)   [64-row tiles]
    gemm_ln<64, true, true, false><<<NV / 64, 256, LnCfg<64>::SMEM>>>(
        inter16, W216, nullptr, pre16, ln2_g, ln2_b, out, nullptr, DI);
}